// round 1
// baseline (speedup 1.0000x reference)
#include <cuda_runtime.h>
#include <math.h>

#define S_LEN   2048
#define DIMV    2048
#define KVD     512
#define NQH     16
#define NKVH    4
#define HDM     128

// ---- scratch (no cudaMalloc allowed) ----
__device__ float g_Q[S_LEN * DIMV];
__device__ float g_K[S_LEN * KVD];
__device__ float g_V[S_LEN * KVD];
__device__ float g_O[S_LEN * DIMV];

// ============================================================
// SGEMM: C[m][n] = sum_k A[m][k] * B[n][k] + bias[n]
// BM=BN=128, BK=16, 256 threads, 8x8 microtile
// ============================================================
__device__ __forceinline__ void gemm_body(
    const float* __restrict__ A, const float* __restrict__ B,
    const float* __restrict__ bias, float* __restrict__ C,
    int N, int K)
{
    __shared__ float As[16 * 128];
    __shared__ float Bs[16 * 128];

    const int tid = threadIdx.x;
    const int bm = blockIdx.y * 128;
    const int bn = blockIdx.x * 128;
    const int ty = tid >> 4;        // 0..15
    const int tx = tid & 15;        // 0..15
    const int lr = tid >> 2;        // 0..63
    const int lk = (tid & 3) << 2;  // 0,4,8,12

    float acc[8][8];
#pragma unroll
    for (int i = 0; i < 8; i++)
#pragma unroll
        for (int j = 0; j < 8; j++) acc[i][j] = 0.f;

    for (int k0 = 0; k0 < K; k0 += 16) {
#pragma unroll
        for (int i = 0; i < 2; i++) {
            int row = lr + (i << 6);
            float4 a4 = *(const float4*)(A + (bm + row) * K + k0 + lk);
            As[(lk + 0) * 128 + row] = a4.x;
            As[(lk + 1) * 128 + row] = a4.y;
            As[(lk + 2) * 128 + row] = a4.z;
            As[(lk + 3) * 128 + row] = a4.w;
            float4 b4 = *(const float4*)(B + (bn + row) * K + k0 + lk);
            Bs[(lk + 0) * 128 + row] = b4.x;
            Bs[(lk + 1) * 128 + row] = b4.y;
            Bs[(lk + 2) * 128 + row] = b4.z;
            Bs[(lk + 3) * 128 + row] = b4.w;
        }
        __syncthreads();
#pragma unroll
        for (int kk = 0; kk < 16; kk++) {
            float a[8], b[8];
            *(float4*)(a)     = *(const float4*)(As + kk * 128 + ty * 8);
            *(float4*)(a + 4) = *(const float4*)(As + kk * 128 + ty * 8 + 4);
            *(float4*)(b)     = *(const float4*)(Bs + kk * 128 + tx * 8);
            *(float4*)(b + 4) = *(const float4*)(Bs + kk * 128 + tx * 8 + 4);
#pragma unroll
            for (int i = 0; i < 8; i++)
#pragma unroll
                for (int j = 0; j < 8; j++)
                    acc[i][j] = fmaf(a[i], b[j], acc[i][j]);
        }
        __syncthreads();
    }

#pragma unroll
    for (int i = 0; i < 8; i++) {
        int row = bm + ty * 8 + i;
#pragma unroll
        for (int j4 = 0; j4 < 2; j4++) {
            int col = bn + tx * 8 + j4 * 4;
            float4 o;
            o.x = acc[i][j4 * 4 + 0] + bias[col + 0];
            o.y = acc[i][j4 * 4 + 1] + bias[col + 1];
            o.z = acc[i][j4 * 4 + 2] + bias[col + 2];
            o.w = acc[i][j4 * 4 + 3] + bias[col + 3];
            *(float4*)(C + row * N + col) = o;
        }
    }
}

__global__ void __launch_bounds__(256) gemm_q_kernel(
    const float* __restrict__ query, const float* __restrict__ Wq,
    const float* __restrict__ bq)
{
    gemm_body(query, Wq, bq, g_Q, DIMV, DIMV);
}

__global__ void __launch_bounds__(256) gemm_kv_kernel(
    const float* __restrict__ key, const float* __restrict__ value,
    const float* __restrict__ Wk, const float* __restrict__ bk,
    const float* __restrict__ Wv, const float* __restrict__ bv)
{
    const float* A  = (blockIdx.z == 0) ? key : value;
    const float* B  = (blockIdx.z == 0) ? Wk  : Wv;
    const float* bb = (blockIdx.z == 0) ? bk  : bv;
    float*       C  = (blockIdx.z == 0) ? g_K : g_V;
    gemm_body(A, B, bb, C, KVD, DIMV);
}

__global__ void __launch_bounds__(256) gemm_o_kernel(
    const float* __restrict__ Wo, const float* __restrict__ bo,
    float* __restrict__ out)
{
    gemm_body(g_O, Wo, bo, out, DIMV, DIMV);
}

// ============================================================
// RoPE (in-place on g_Q, g_K). adjusted_base == 10000 exactly
// for S=2048 (base_adj = 1). One thread per (s, head, pair j).
// ============================================================
__global__ void __launch_bounds__(256) rope_kernel()
{
    const int total = S_LEN * (NQH + NKVH) * 64;
    int idx = blockIdx.x * blockDim.x + threadIdx.x;
    if (idx >= total) return;
    int j  = idx & 63;
    int t  = idx >> 6;
    int hh = t % (NQH + NKVH);
    int s  = t / (NQH + NKVH);

    float inv = powf(10000.0f, -(float)(2 * j) * (1.0f / 128.0f));
    float ang = (float)s * inv;
    float sn, cs;
    sincosf(ang, &sn, &cs);   // accurate range reduction (angles up to 2048 rad)

    float* base = (hh < NQH) ? (g_Q + s * DIMV + hh * HDM)
                             : (g_K + s * KVD + (hh - NQH) * HDM);
    float x1 = base[j];
    float x2 = base[j + 64];
    base[j]      = x1 * cs - x2 * sn;
    base[j + 64] = x2 * cs + x1 * sn;
}

// ============================================================
// Flash attention (causal, GQA): BM=BN=64, HD=128, fp32
// grid (32 qtiles, 16 heads), 256 threads.
// Dynamic smem: sQ[64][128], sKT[128][64], sV[64][128],
//               sS[64][65], m/l/scale[64 each]  = 115712 B
// ============================================================
#define ATT_SMEM ((8192 + 8192 + 8192 + 64 * 65 + 192) * 4)

__global__ void __launch_bounds__(256) attn_kernel()
{
    extern __shared__ float sm[];
    float* sQ   = sm;                 // [64][128] row-major
    float* sKT  = sm + 8192;          // [128][64] d-major (transposed K)
    float* sV   = sm + 16384;         // [64][128] row-major
    float* sS   = sm + 24576;         // [64][65]
    float* mrow = sm + 24576 + 64 * 65;
    float* lrow = mrow + 64;
    float* srow = lrow + 64;

    const int tid = threadIdx.x;
    const int qt  = gridDim.x - 1 - blockIdx.x;  // heavy blocks first
    const int h   = blockIdx.y;
    const int kvh = h >> 2;
    const int ty  = tid >> 4;   // 0..15
    const int tx  = tid & 15;   // 0..15

    const float* Qb = g_Q + h * HDM;
    const float* Kb = g_K + kvh * HDM;
    const float* Vb = g_V + kvh * HDM;

    // load Q tile (64 x 128): 2048 float4, 8 per thread
#pragma unroll
    for (int r = 0; r < 8; r++) {
        int li  = tid + r * 256;
        int row = li >> 5;
        int c4  = li & 31;
        *(float4*)(sQ + row * 128 + c4 * 4) =
            *(const float4*)(Qb + (qt * 64 + row) * DIMV + c4 * 4);
    }
    if (tid < 64) { mrow[tid] = -3.0e38f; lrow[tid] = 0.f; }

    float acc[4][8];
#pragma unroll
    for (int i = 0; i < 4; i++)
#pragma unroll
        for (int c = 0; c < 8; c++) acc[i][c] = 0.f;

    const float scale = 0.08838834764831845f;  // 1/sqrt(128)

    for (int j = 0; j <= qt; j++) {
        __syncthreads();  // previous consumers done before overwriting smem

        // load K tile transposed: sKT[d][n]
#pragma unroll
        for (int r = 0; r < 8; r++) {
            int li = tid + r * 256;   // li = dg*64 + n
            int dg = li >> 6;         // 0..31
            int n  = li & 63;
            float4 v = *(const float4*)(Kb + (j * 64 + n) * KVD + dg * 4);
            sKT[(dg * 4 + 0) * 64 + n] = v.x;
            sKT[(dg * 4 + 1) * 64 + n] = v.y;
            sKT[(dg * 4 + 2) * 64 + n] = v.z;
            sKT[(dg * 4 + 3) * 64 + n] = v.w;
        }
        // load V tile row-major
#pragma unroll
        for (int r = 0; r < 8; r++) {
            int li  = tid + r * 256;
            int row = li >> 5;
            int c4  = li & 31;
            *(float4*)(sV + row * 128 + c4 * 4) =
                *(const float4*)(Vb + (j * 64 + row) * KVD + c4 * 4);
        }
        __syncthreads();

        // S = (Q K^T) * scale, 4x4 microtile per thread
        float s4[4][4];
#pragma unroll
        for (int i = 0; i < 4; i++)
#pragma unroll
            for (int c = 0; c < 4; c++) s4[i][c] = 0.f;

#pragma unroll 4
        for (int d = 0; d < 128; d++) {
            float4 b4 = *(const float4*)(sKT + d * 64 + tx * 4);
            float bb[4] = {b4.x, b4.y, b4.z, b4.w};
#pragma unroll
            for (int i = 0; i < 4; i++) {
                float a = sQ[(ty * 4 + i) * 128 + d];
#pragma unroll
                for (int c = 0; c < 4; c++)
                    s4[i][c] = fmaf(a, bb[c], s4[i][c]);
            }
        }
        // mask + scale + store to sS
#pragma unroll
        for (int i = 0; i < 4; i++) {
            int qr = qt * 64 + ty * 4 + i;
#pragma unroll
            for (int c = 0; c < 4; c++) {
                int kr = j * 64 + tx * 4 + c;
                float val = (kr <= qr) ? s4[i][c] * scale : -3.0e38f;
                sS[(ty * 4 + i) * 65 + tx * 4 + c] = val;
            }
        }
        __syncthreads();

        // online softmax, one thread per row
        if (tid < 64) {
            float mo = mrow[tid];
            float mx = mo;
#pragma unroll 8
            for (int c = 0; c < 64; c++)
                mx = fmaxf(mx, sS[tid * 65 + c]);
            float scl = __expf(mo - mx);
            float sum = 0.f;
#pragma unroll 8
            for (int c = 0; c < 64; c++) {
                float p = __expf(sS[tid * 65 + c] - mx);
                sS[tid * 65 + c] = p;
                sum += p;
            }
            lrow[tid] = lrow[tid] * scl + sum;
            mrow[tid] = mx;
            srow[tid] = scl;
        }
        __syncthreads();

        // rescale acc, then acc += P @ V  (cols interleaved: tx + c*16)
#pragma unroll
        for (int i = 0; i < 4; i++) {
            float rs = srow[ty * 4 + i];
#pragma unroll
            for (int c = 0; c < 8; c++) acc[i][c] *= rs;
        }
#pragma unroll 4
        for (int k = 0; k < 64; k++) {
            float p[4];
#pragma unroll
            for (int i = 0; i < 4; i++)
                p[i] = sS[(ty * 4 + i) * 65 + k];
#pragma unroll
            for (int c = 0; c < 8; c++) {
                float v = sV[k * 128 + tx + c * 16];
#pragma unroll
                for (int i = 0; i < 4; i++)
                    acc[i][c] = fmaf(p[i], v, acc[i][c]);
            }
        }
    }

    // epilogue: divide by l, write to g_O (S, DIM) layout
#pragma unroll
    for (int i = 0; i < 4; i++) {
        int row = ty * 4 + i;
        float invl = 1.0f / lrow[row];
#pragma unroll
        for (int c = 0; c < 8; c++) {
            g_O[(qt * 64 + row) * DIMV + h * HDM + tx + c * 16] = acc[i][c] * invl;
        }
    }
}

// ============================================================
// launch
// ============================================================
extern "C" void kernel_launch(void* const* d_in, const int* in_sizes, int n_in,
                              void* d_out, int out_size)
{
    const float* query = (const float*)d_in[0];
    const float* key   = (const float*)d_in[1];
    const float* value = (const float*)d_in[2];
    const float* Wq    = (const float*)d_in[3];
    const float* bq    = (const float*)d_in[4];
    const float* Wk    = (const float*)d_in[5];
    const float* bk    = (const float*)d_in[6];
    const float* Wv    = (const float*)d_in[7];
    const float* bv    = (const float*)d_in[8];
    const float* Wo    = (const float*)d_in[9];
    const float* bo    = (const float*)d_in[10];
    float* out = (float*)d_out;

    gemm_q_kernel<<<dim3(16, 16), 256>>>(query, Wq, bq);
    gemm_kv_kernel<<<dim3(4, 16, 2), 256>>>(key, value, Wk, bk, Wv, bv);

    {
        const int total = S_LEN * (NQH + NKVH) * 64;
        rope_kernel<<<(total + 255) / 256, 256>>>();
    }

    // attribute set is idempotent; persists from the pre-capture correctness call
    cudaFuncSetAttribute((const void*)attn_kernel,
                         cudaFuncAttributeMaxDynamicSharedMemorySize, ATT_SMEM);
    attn_kernel<<<dim3(32, 16), 256, ATT_SMEM>>>();

    gemm_o_kernel<<<dim3(16, 16), 256>>>(Wo, bo, out);
}

// round 2
// speedup vs baseline: 1.5484x; 1.5484x over previous
#include <cuda_runtime.h>
#include <math.h>

#define S_LEN   2048
#define DIMV    2048
#define KVD     512
#define NQH     16
#define NKVH    4
#define HDM     128

// ---- scratch (no cudaMalloc allowed) ----
__device__ float g_Q[S_LEN * DIMV];
__device__ float g_K[S_LEN * KVD];
__device__ float g_V[S_LEN * KVD];
__device__ float g_O[S_LEN * DIMV];

// ============================================================
// tf32 tensor-core GEMM:  C[m][n] = sum_k A[m][k]*B[n][k] + bias[n]
// BM=BN=128, BK=16, 256 thr / 8 warps (2x4 grid, 64x32 warp tile)
// mma.sync.m16n8k8.row.col.f32.tf32.tf32.f32
// ============================================================
#define TFS 136   // smem row stride (k-major): (8k+m)%32 distinct -> conflict-free LDS

__device__ __forceinline__ unsigned f2tf(float f) {
    unsigned u;
    asm("cvt.rna.tf32.f32 %0, %1;" : "=r"(u) : "f"(f));
    return u;
}

__device__ __forceinline__ void mma_tf32(float* c, const unsigned* a, const unsigned* b) {
    asm volatile(
        "mma.sync.aligned.m16n8k8.row.col.f32.tf32.tf32.f32 "
        "{%0,%1,%2,%3}, {%4,%5,%6,%7}, {%8,%9}, {%0,%1,%2,%3};"
        : "+f"(c[0]), "+f"(c[1]), "+f"(c[2]), "+f"(c[3])
        : "r"(a[0]), "r"(a[1]), "r"(a[2]), "r"(a[3]), "r"(b[0]), "r"(b[1]));
}

__device__ __forceinline__ void gemm_tf32_body(
    const float* __restrict__ A, const float* __restrict__ B,
    const float* __restrict__ bias, float* __restrict__ C,
    int N, int K)
{
    __shared__ unsigned As[16 * TFS];
    __shared__ unsigned Bs[16 * TFS];

    const int tid  = threadIdx.x;
    const int lane = tid & 31;
    const int wid  = tid >> 5;
    const int wm   = (wid >> 2) * 64;   // warp m offset (0,64)
    const int wn   = (wid & 3) * 32;    // warp n offset (0..96)
    const int lg   = lane >> 2;         // group 0..7
    const int lc   = lane & 3;          // 0..3

    const int bm = blockIdx.y * 128;
    const int bn = blockIdx.x * 128;

    // loader mapping: 512 float4 per tile, 2 per thread
    const int l_row0 = tid >> 2;        // 0..63
    const int l_c4   = tid & 3;         // float4 col
    const int l_k    = l_c4 * 4;

    float acc[4][4][4];
#pragma unroll
    for (int i = 0; i < 4; i++)
#pragma unroll
        for (int j = 0; j < 4; j++)
#pragma unroll
            for (int c = 0; c < 4; c++) acc[i][j][c] = 0.f;

    const int nIter = K >> 4;

    float4 pa0, pa1, pb0, pb1;
    // preload iter 0
    pa0 = *(const float4*)(A + (bm + l_row0)      * K + l_k);
    pa1 = *(const float4*)(A + (bm + l_row0 + 64) * K + l_k);
    pb0 = *(const float4*)(B + (bn + l_row0)      * K + l_k);
    pb1 = *(const float4*)(B + (bn + l_row0 + 64) * K + l_k);

    for (int kt = 0; kt < nIter; kt++) {
        // STS (tf32-converted, k-major layout)
        {
            const float* va0 = (const float*)&pa0;
            const float* va1 = (const float*)&pa1;
            const float* vb0 = (const float*)&pb0;
            const float* vb1 = (const float*)&pb1;
#pragma unroll
            for (int x = 0; x < 4; x++) {
                As[(l_k + x) * TFS + l_row0]      = f2tf(va0[x]);
                As[(l_k + x) * TFS + l_row0 + 64] = f2tf(va1[x]);
                Bs[(l_k + x) * TFS + l_row0]      = f2tf(vb0[x]);
                Bs[(l_k + x) * TFS + l_row0 + 64] = f2tf(vb1[x]);
            }
        }
        __syncthreads();

        // preload next tile
        if (kt + 1 < nIter) {
            const float* An = A + (kt + 1) * 16;
            const float* Bn = B + (kt + 1) * 16;
            pa0 = *(const float4*)(An + (bm + l_row0)      * K + l_k);
            pa1 = *(const float4*)(An + (bm + l_row0 + 64) * K + l_k);
            pb0 = *(const float4*)(Bn + (bn + l_row0)      * K + l_k);
            pb1 = *(const float4*)(Bn + (bn + l_row0 + 64) * K + l_k);
        }

        // 2 k8 steps of MMA
#pragma unroll
        for (int ks = 0; ks < 2; ks++) {
            const int k0 = ks * 8;
            unsigned af[4][4], bf[4][2];
#pragma unroll
            for (int mt = 0; mt < 4; mt++) {
                int rm = wm + mt * 16 + lg;
                af[mt][0] = As[(k0 + lc)     * TFS + rm];
                af[mt][1] = As[(k0 + lc)     * TFS + rm + 8];
                af[mt][2] = As[(k0 + lc + 4) * TFS + rm];
                af[mt][3] = As[(k0 + lc + 4) * TFS + rm + 8];
            }
#pragma unroll
            for (int nt = 0; nt < 4; nt++) {
                int cn = wn + nt * 8 + lg;
                bf[nt][0] = Bs[(k0 + lc)     * TFS + cn];
                bf[nt][1] = Bs[(k0 + lc + 4) * TFS + cn];
            }
#pragma unroll
            for (int mt = 0; mt < 4; mt++)
#pragma unroll
                for (int nt = 0; nt < 4; nt++)
                    mma_tf32(acc[mt][nt], af[mt], bf[nt]);
        }
        __syncthreads();
    }

    // epilogue: c0,c1 at (row, 2lc / 2lc+1), c2,c3 at (row+8, ...)
#pragma unroll
    for (int mt = 0; mt < 4; mt++) {
#pragma unroll
        for (int nt = 0; nt < 4; nt++) {
            int row = bm + wm + mt * 16 + lg;
            int col = bn + wn + nt * 8 + 2 * lc;
            float b0 = __ldg(bias + col);
            float b1 = __ldg(bias + col + 1);
            float2 v0 = make_float2(acc[mt][nt][0] + b0, acc[mt][nt][1] + b1);
            float2 v1 = make_float2(acc[mt][nt][2] + b0, acc[mt][nt][3] + b1);
            *(float2*)(C + row * N + col)       = v0;
            *(float2*)(C + (row + 8) * N + col) = v1;
        }
    }
}

__global__ void __launch_bounds__(256) gemm_q_kernel(
    const float* __restrict__ query, const float* __restrict__ Wq,
    const float* __restrict__ bq)
{
    gemm_tf32_body(query, Wq, bq, g_Q, DIMV, DIMV);
}

__global__ void __launch_bounds__(256) gemm_kv_kernel(
    const float* __restrict__ key, const float* __restrict__ value,
    const float* __restrict__ Wk, const float* __restrict__ bk,
    const float* __restrict__ Wv, const float* __restrict__ bv)
{
    const float* A  = (blockIdx.z == 0) ? key : value;
    const float* B  = (blockIdx.z == 0) ? Wk  : Wv;
    const float* bb = (blockIdx.z == 0) ? bk  : bv;
    float*       C  = (blockIdx.z == 0) ? g_K : g_V;
    gemm_tf32_body(A, B, bb, C, KVD, DIMV);
}

__global__ void __launch_bounds__(256) gemm_o_kernel(
    const float* __restrict__ Wo, const float* __restrict__ bo,
    float* __restrict__ out)
{
    gemm_tf32_body(g_O, Wo, bo, out, DIMV, DIMV);
}

// ============================================================
// RoPE (in-place on g_Q, g_K). adjusted_base == 10000 exactly.
// ============================================================
__global__ void __launch_bounds__(256) rope_kernel()
{
    const int total = S_LEN * (NQH + NKVH) * 64;
    int idx = blockIdx.x * blockDim.x + threadIdx.x;
    if (idx >= total) return;
    int j  = idx & 63;
    int t  = idx >> 6;
    int hh = t % (NQH + NKVH);
    int s  = t / (NQH + NKVH);

    float inv = powf(10000.0f, -(float)(2 * j) * (1.0f / 128.0f));
    float ang = (float)s * inv;
    float sn, cs;
    sincosf(ang, &sn, &cs);

    float* base = (hh < NQH) ? (g_Q + s * DIMV + hh * HDM)
                             : (g_K + s * KVD + (hh - NQH) * HDM);
    float x1 = base[j];
    float x2 = base[j + 64];
    base[j]      = x1 * cs - x2 * sn;
    base[j + 64] = x2 * cs + x1 * sn;
}

// ============================================================
// Flash attention (causal, GQA): BM=BN=64, HD=128, fp32
// ============================================================
#define ATT_SMEM ((8192 + 8192 + 8192 + 64 * 65 + 192) * 4)

__global__ void __launch_bounds__(256) attn_kernel()
{
    extern __shared__ float sm[];
    float* sQ   = sm;                 // [64][128] row-major
    float* sKT  = sm + 8192;          // [128][64] d-major (transposed K)
    float* sV   = sm + 16384;         // [64][128] row-major
    float* sS   = sm + 24576;         // [64][65]
    float* mrow = sm + 24576 + 64 * 65;
    float* lrow = mrow + 64;
    float* srow = lrow + 64;

    const int tid = threadIdx.x;
    const int qt  = gridDim.x - 1 - blockIdx.x;  // heavy blocks first
    const int h   = blockIdx.y;
    const int kvh = h >> 2;
    const int ty  = tid >> 4;   // 0..15
    const int tx  = tid & 15;   // 0..15

    const float* Qb = g_Q + h * HDM;
    const float* Kb = g_K + kvh * HDM;
    const float* Vb = g_V + kvh * HDM;

#pragma unroll
    for (int r = 0; r < 8; r++) {
        int li  = tid + r * 256;
        int row = li >> 5;
        int c4  = li & 31;
        *(float4*)(sQ + row * 128 + c4 * 4) =
            *(const float4*)(Qb + (qt * 64 + row) * DIMV + c4 * 4);
    }
    if (tid < 64) { mrow[tid] = -3.0e38f; lrow[tid] = 0.f; }

    float acc[4][8];
#pragma unroll
    for (int i = 0; i < 4; i++)
#pragma unroll
        for (int c = 0; c < 8; c++) acc[i][c] = 0.f;

    const float scale = 0.08838834764831845f;  // 1/sqrt(128)

    for (int j = 0; j <= qt; j++) {
        __syncthreads();

#pragma unroll
        for (int r = 0; r < 8; r++) {
            int li = tid + r * 256;
            int dg = li >> 6;
            int n  = li & 63;
            float4 v = *(const float4*)(Kb + (j * 64 + n) * KVD + dg * 4);
            sKT[(dg * 4 + 0) * 64 + n] = v.x;
            sKT[(dg * 4 + 1) * 64 + n] = v.y;
            sKT[(dg * 4 + 2) * 64 + n] = v.z;
            sKT[(dg * 4 + 3) * 64 + n] = v.w;
        }
#pragma unroll
        for (int r = 0; r < 8; r++) {
            int li  = tid + r * 256;
            int row = li >> 5;
            int c4  = li & 31;
            *(float4*)(sV + row * 128 + c4 * 4) =
                *(const float4*)(Vb + (j * 64 + row) * KVD + c4 * 4);
        }
        __syncthreads();

        float s4[4][4];
#pragma unroll
        for (int i = 0; i < 4; i++)
#pragma unroll
            for (int c = 0; c < 4; c++) s4[i][c] = 0.f;

#pragma unroll 4
        for (int d = 0; d < 128; d++) {
            float4 b4 = *(const float4*)(sKT + d * 64 + tx * 4);
            float bb[4] = {b4.x, b4.y, b4.z, b4.w};
#pragma unroll
            for (int i = 0; i < 4; i++) {
                float a = sQ[(ty * 4 + i) * 128 + d];
#pragma unroll
                for (int c = 0; c < 4; c++)
                    s4[i][c] = fmaf(a, bb[c], s4[i][c]);
            }
        }
#pragma unroll
        for (int i = 0; i < 4; i++) {
            int qr = qt * 64 + ty * 4 + i;
#pragma unroll
            for (int c = 0; c < 4; c++) {
                int kr = j * 64 + tx * 4 + c;
                float val = (kr <= qr) ? s4[i][c] * scale : -3.0e38f;
                sS[(ty * 4 + i) * 65 + tx * 4 + c] = val;
            }
        }
        __syncthreads();

        if (tid < 64) {
            float mo = mrow[tid];
            float mx = mo;
#pragma unroll 8
            for (int c = 0; c < 64; c++)
                mx = fmaxf(mx, sS[tid * 65 + c]);
            float scl = __expf(mo - mx);
            float sum = 0.f;
#pragma unroll 8
            for (int c = 0; c < 64; c++) {
                float p = __expf(sS[tid * 65 + c] - mx);
                sS[tid * 65 + c] = p;
                sum += p;
            }
            lrow[tid] = lrow[tid] * scl + sum;
            mrow[tid] = mx;
            srow[tid] = scl;
        }
        __syncthreads();

#pragma unroll
        for (int i = 0; i < 4; i++) {
            float rs = srow[ty * 4 + i];
#pragma unroll
            for (int c = 0; c < 8; c++) acc[i][c] *= rs;
        }
#pragma unroll 4
        for (int k = 0; k < 64; k++) {
            float p[4];
#pragma unroll
            for (int i = 0; i < 4; i++)
                p[i] = sS[(ty * 4 + i) * 65 + k];
#pragma unroll
            for (int c = 0; c < 8; c++) {
                float v = sV[k * 128 + tx + c * 16];
#pragma unroll
                for (int i = 0; i < 4; i++)
                    acc[i][c] = fmaf(p[i], v, acc[i][c]);
            }
        }
    }

#pragma unroll
    for (int i = 0; i < 4; i++) {
        int row = ty * 4 + i;
        float invl = 1.0f / lrow[row];
#pragma unroll
        for (int c = 0; c < 8; c++) {
            g_O[(qt * 64 + row) * DIMV + h * HDM + tx + c * 16] = acc[i][c] * invl;
        }
    }
}

// ============================================================
// launch
// ============================================================
extern "C" void kernel_launch(void* const* d_in, const int* in_sizes, int n_in,
                              void* d_out, int out_size)
{
    const float* query = (const float*)d_in[0];
    const float* key   = (const float*)d_in[1];
    const float* value = (const float*)d_in[2];
    const float* Wq    = (const float*)d_in[3];
    const float* bq    = (const float*)d_in[4];
    const float* Wk    = (const float*)d_in[5];
    const float* bk    = (const float*)d_in[6];
    const float* Wv    = (const float*)d_in[7];
    const float* bv    = (const float*)d_in[8];
    const float* Wo    = (const float*)d_in[9];
    const float* bo    = (const float*)d_in[10];
    float* out = (float*)d_out;

    gemm_q_kernel<<<dim3(16, 16), 256>>>(query, Wq, bq);
    gemm_kv_kernel<<<dim3(4, 16, 2), 256>>>(key, value, Wk, bk, Wv, bv);

    {
        const int total = S_LEN * (NQH + NKVH) * 64;
        rope_kernel<<<(total + 255) / 256, 256>>>();
    }

    cudaFuncSetAttribute((const void*)attn_kernel,
                         cudaFuncAttributeMaxDynamicSharedMemorySize, ATT_SMEM);
    attn_kernel<<<dim3(32, 16), 256, ATT_SMEM>>>();

    gemm_o_kernel<<<dim3(16, 16), 256>>>(Wo, bo, out);
}

// round 3
// speedup vs baseline: 2.6319x; 1.6997x over previous
#include <cuda_runtime.h>
#include <math.h>

#define S_LEN   2048
#define DIMV    2048
#define KVD     512
#define NQH     16
#define NKVH    4
#define HDM     128

// ---- scratch (no cudaMalloc allowed) ----
__device__ float g_Q[S_LEN * DIMV];
__device__ float g_K[S_LEN * KVD];
__device__ float g_V[S_LEN * KVD];
__device__ float g_O[S_LEN * DIMV];

// ============================================================
// common tf32 helpers
// ============================================================
__device__ __forceinline__ unsigned f2tf(float f) {
    unsigned u;
    asm("cvt.rna.tf32.f32 %0, %1;" : "=r"(u) : "f"(f));
    return u;
}

__device__ __forceinline__ void mma_tf32(float* c, const unsigned* a, const unsigned* b) {
    asm volatile(
        "mma.sync.aligned.m16n8k8.row.col.f32.tf32.tf32.f32 "
        "{%0,%1,%2,%3}, {%4,%5,%6,%7}, {%8,%9}, {%0,%1,%2,%3};"
        : "+f"(c[0]), "+f"(c[1]), "+f"(c[2]), "+f"(c[3])
        : "r"(a[0]), "r"(a[1]), "r"(a[2]), "r"(a[3]), "r"(b[0]), "r"(b[1]));
}

__device__ __forceinline__ void cp16(unsigned dst, const void* src) {
    asm volatile("cp.async.cg.shared.global [%0], [%1], 16;" :: "r"(dst), "l"(src));
}
__device__ __forceinline__ void cp_commit() {
    asm volatile("cp.async.commit_group;");
}
__device__ __forceinline__ void cp_wait0() {
    asm volatile("cp.async.wait_group 0;" ::: "memory");
}

// ============================================================
// tf32 tensor-core GEMM:  C[m][n] = sum_k A[m][k]*B[n][k] + bias[n]
// BM=BN=128, BK=16, 256 thr / 8 warps (2x4 grid, 64x32 warp tile)
// ============================================================
#define TFS 136

__device__ __forceinline__ void gemm_tf32_body(
    const float* __restrict__ A, const float* __restrict__ B,
    const float* __restrict__ bias, float* __restrict__ C,
    int N, int K)
{
    __shared__ unsigned As[16 * TFS];
    __shared__ unsigned Bs[16 * TFS];

    const int tid  = threadIdx.x;
    const int lane = tid & 31;
    const int wid  = tid >> 5;
    const int wm   = (wid >> 2) * 64;
    const int wn   = (wid & 3) * 32;
    const int lg   = lane >> 2;
    const int lc   = lane & 3;

    const int bm = blockIdx.y * 128;
    const int bn = blockIdx.x * 128;

    const int l_row0 = tid >> 2;
    const int l_k    = (tid & 3) * 4;

    float acc[4][4][4];
#pragma unroll
    for (int i = 0; i < 4; i++)
#pragma unroll
        for (int j = 0; j < 4; j++)
#pragma unroll
            for (int c = 0; c < 4; c++) acc[i][j][c] = 0.f;

    const int nIter = K >> 4;

    float4 pa0, pa1, pb0, pb1;
    pa0 = *(const float4*)(A + (bm + l_row0)      * K + l_k);
    pa1 = *(const float4*)(A + (bm + l_row0 + 64) * K + l_k);
    pb0 = *(const float4*)(B + (bn + l_row0)      * K + l_k);
    pb1 = *(const float4*)(B + (bn + l_row0 + 64) * K + l_k);

    for (int kt = 0; kt < nIter; kt++) {
        {
            const float* va0 = (const float*)&pa0;
            const float* va1 = (const float*)&pa1;
            const float* vb0 = (const float*)&pb0;
            const float* vb1 = (const float*)&pb1;
#pragma unroll
            for (int x = 0; x < 4; x++) {
                As[(l_k + x) * TFS + l_row0]      = f2tf(va0[x]);
                As[(l_k + x) * TFS + l_row0 + 64] = f2tf(va1[x]);
                Bs[(l_k + x) * TFS + l_row0]      = f2tf(vb0[x]);
                Bs[(l_k + x) * TFS + l_row0 + 64] = f2tf(vb1[x]);
            }
        }
        __syncthreads();

        if (kt + 1 < nIter) {
            const float* An = A + (kt + 1) * 16;
            const float* Bn = B + (kt + 1) * 16;
            pa0 = *(const float4*)(An + (bm + l_row0)      * K + l_k);
            pa1 = *(const float4*)(An + (bm + l_row0 + 64) * K + l_k);
            pb0 = *(const float4*)(Bn + (bn + l_row0)      * K + l_k);
            pb1 = *(const float4*)(Bn + (bn + l_row0 + 64) * K + l_k);
        }

#pragma unroll
        for (int ks = 0; ks < 2; ks++) {
            const int k0 = ks * 8;
            unsigned af[4][4], bf[4][2];
#pragma unroll
            for (int mt = 0; mt < 4; mt++) {
                int rm = wm + mt * 16 + lg;
                af[mt][0] = As[(k0 + lc)     * TFS + rm];
                af[mt][1] = As[(k0 + lc)     * TFS + rm + 8];
                af[mt][2] = As[(k0 + lc + 4) * TFS + rm];
                af[mt][3] = As[(k0 + lc + 4) * TFS + rm + 8];
            }
#pragma unroll
            for (int nt = 0; nt < 4; nt++) {
                int cn = wn + nt * 8 + lg;
                bf[nt][0] = Bs[(k0 + lc)     * TFS + cn];
                bf[nt][1] = Bs[(k0 + lc + 4) * TFS + cn];
            }
#pragma unroll
            for (int mt = 0; mt < 4; mt++)
#pragma unroll
                for (int nt = 0; nt < 4; nt++)
                    mma_tf32(acc[mt][nt], af[mt], bf[nt]);
        }
        __syncthreads();
    }

#pragma unroll
    for (int mt = 0; mt < 4; mt++) {
#pragma unroll
        for (int nt = 0; nt < 4; nt++) {
            int row = bm + wm + mt * 16 + lg;
            int col = bn + wn + nt * 8 + 2 * lc;
            float b0 = __ldg(bias + col);
            float b1 = __ldg(bias + col + 1);
            float2 v0 = make_float2(acc[mt][nt][0] + b0, acc[mt][nt][1] + b1);
            float2 v1 = make_float2(acc[mt][nt][2] + b0, acc[mt][nt][3] + b1);
            *(float2*)(C + row * N + col)       = v0;
            *(float2*)(C + (row + 8) * N + col) = v1;
        }
    }
}

__global__ void __launch_bounds__(256) gemm_q_kernel(
    const float* __restrict__ query, const float* __restrict__ Wq,
    const float* __restrict__ bq)
{
    gemm_tf32_body(query, Wq, bq, g_Q, DIMV, DIMV);
}

__global__ void __launch_bounds__(256) gemm_kv_kernel(
    const float* __restrict__ key, const float* __restrict__ value,
    const float* __restrict__ Wk, const float* __restrict__ bk,
    const float* __restrict__ Wv, const float* __restrict__ bv)
{
    const float* A  = (blockIdx.z == 0) ? key : value;
    const float* B  = (blockIdx.z == 0) ? Wk  : Wv;
    const float* bb = (blockIdx.z == 0) ? bk  : bv;
    float*       C  = (blockIdx.z == 0) ? g_K : g_V;
    gemm_tf32_body(A, B, bb, C, KVD, DIMV);
}

__global__ void __launch_bounds__(256) gemm_o_kernel(
    const float* __restrict__ Wo, const float* __restrict__ bo,
    float* __restrict__ out)
{
    gemm_tf32_body(g_O, Wo, bo, out, DIMV, DIMV);
}

// ============================================================
// RoPE
// ============================================================
__global__ void __launch_bounds__(256) rope_kernel()
{
    const int total = S_LEN * (NQH + NKVH) * 64;
    int idx = blockIdx.x * blockDim.x + threadIdx.x;
    if (idx >= total) return;
    int j  = idx & 63;
    int t  = idx >> 6;
    int hh = t % (NQH + NKVH);
    int s  = t / (NQH + NKVH);

    float inv = powf(10000.0f, -(float)(2 * j) * (1.0f / 128.0f));
    float ang = (float)s * inv;
    float sn, cs;
    sincosf(ang, &sn, &cs);

    float* base = (hh < NQH) ? (g_Q + s * DIMV + hh * HDM)
                             : (g_K + s * KVD + (hh - NQH) * HDM);
    float x1 = base[j];
    float x2 = base[j + 64];
    base[j]      = x1 * cs - x2 * sn;
    base[j + 64] = x2 * cs + x1 * sn;
}

// ============================================================
// Flash attention with tf32 MMA, causal GQA
// BM=BN=64, HD=128, 256 thr / 8 warps.
// smem layout (floats):
//   Qst   [64][132]  tf32 (staging; frags then live in regs)
//   K     2x [64][132] raw f32 (double buffer, cp.async)
//   V     2x [64][136] raw f32
//   sS    [64][68]    S scores (f32) -> P (tf32 in place)
//   stats m/l/esc [64] each
// ============================================================
#define AQ_ST 0
#define AK_ST 8448
#define AV_ST 25344
#define AS_ST 42752
#define AST_M 47104
#define AST_L 47168
#define AST_S 47232
#define A_TOT 47296
#define ATT_SMEM (A_TOT * 4)

__device__ __forceinline__ void attn_issue_kv(
    const float* Kb, const float* Vb, int j, int buf,
    unsigned smem_base, int tid)
{
    const float* Ksrc = Kb + (j * 64) * KVD;
    const float* Vsrc = Vb + (j * 64) * KVD;
    unsigned kb = smem_base + (AK_ST + buf * 8448) * 4;
    unsigned vb = smem_base + (AV_ST + buf * 8704) * 4;
#pragma unroll
    for (int i = 0; i < 8; i++) {
        int c   = tid + i * 256;
        int row = c >> 5;
        int q16 = c & 31;
        cp16(kb + (row * 132 + q16 * 4) * 4, Ksrc + row * KVD + q16 * 4);
        cp16(vb + (row * 136 + q16 * 4) * 4, Vsrc + row * KVD + q16 * 4);
    }
    cp_commit();
}

__global__ void __launch_bounds__(256) attn_kernel()
{
    extern __shared__ float sm[];
    unsigned smem_base = (unsigned)__cvta_generic_to_shared(sm);

    const int tid  = threadIdx.x;
    const int lane = tid & 31;
    const int wid  = tid >> 5;
    const int qt   = gridDim.x - 1 - blockIdx.x;  // heavy blocks first
    const int h    = blockIdx.y;
    const int kvh  = h >> 2;
    const int lg   = lane >> 2;
    const int lc   = lane & 3;

    // S-warp tile: 32x16 (2 m-tiles x 2 n-tiles), warps 2x4
    const int wms = (wid >> 2) * 32;
    const int wns = (wid & 3) * 16;
    // PV-warp tile: 32x32 (2 m-tiles x 4 n-tiles)
    const int wmp = (wid >> 2) * 32;
    const int wnp = (wid & 3) * 32;

    const float* Qb = g_Q + h * HDM;
    const float* Kb = g_K + kvh * HDM;
    const float* Vb = g_V + kvh * HDM;

    // kick off K/V tile 0
    attn_issue_kv(Kb, Vb, 0, 0, smem_base, tid);

    // stage Q (scaled + tf32)
    const float scale = 0.08838834764831845f;  // 1/sqrt(128)
    unsigned* Qst = (unsigned*)(sm + AQ_ST);
#pragma unroll
    for (int i = 0; i < 8; i++) {
        int li  = tid + i * 256;
        int row = li >> 5;
        int c4  = li & 31;
        float4 v = *(const float4*)(Qb + (qt * 64 + row) * DIMV + c4 * 4);
        uint4 u;
        u.x = f2tf(v.x * scale); u.y = f2tf(v.y * scale);
        u.z = f2tf(v.z * scale); u.w = f2tf(v.w * scale);
        *(uint4*)(Qst + row * 132 + c4 * 4) = u;
    }
    if (tid < 64) { sm[AST_M + tid] = -1e30f; sm[AST_L + tid] = 0.f; }
    __syncthreads();

    // Q fragments -> registers (reused every iteration)
    unsigned qf[2][16][4];
#pragma unroll
    for (int mt = 0; mt < 2; mt++) {
        int rm = wms + mt * 16 + lg;
#pragma unroll
        for (int ks = 0; ks < 16; ks++) {
            qf[mt][ks][0] = Qst[rm * 132 + ks * 8 + lc];
            qf[mt][ks][1] = Qst[(rm + 8) * 132 + ks * 8 + lc];
            qf[mt][ks][2] = Qst[rm * 132 + ks * 8 + lc + 4];
            qf[mt][ks][3] = Qst[(rm + 8) * 132 + ks * 8 + lc + 4];
        }
    }

    float oacc[2][4][4];
#pragma unroll
    for (int mt = 0; mt < 2; mt++)
#pragma unroll
        for (int nt = 0; nt < 4; nt++)
#pragma unroll
            for (int c = 0; c < 4; c++) oacc[mt][nt][c] = 0.f;

    int buf = 0;
    for (int j = 0; j <= qt; j++) {
        cp_wait0();
        __syncthreads();
        if (j < qt) attn_issue_kv(Kb, Vb, j + 1, buf ^ 1, smem_base, tid);

        // ---- S = Q K^T (tf32 MMA) ----
        const float* Ks = sm + AK_ST + buf * 8448;
        float sacc[2][2][4];
#pragma unroll
        for (int mt = 0; mt < 2; mt++)
#pragma unroll
            for (int nt = 0; nt < 2; nt++)
#pragma unroll
                for (int c = 0; c < 4; c++) sacc[mt][nt][c] = 0.f;

#pragma unroll
        for (int ks = 0; ks < 16; ks++) {
            unsigned bf[2][2];
#pragma unroll
            for (int nt = 0; nt < 2; nt++) {
                int cn = wns + nt * 8 + lg;
                bf[nt][0] = f2tf(Ks[cn * 132 + ks * 8 + lc]);
                bf[nt][1] = f2tf(Ks[cn * 132 + ks * 8 + lc + 4]);
            }
#pragma unroll
            for (int mt = 0; mt < 2; mt++)
#pragma unroll
                for (int nt = 0; nt < 2; nt++)
                    mma_tf32(sacc[mt][nt], qf[mt][ks], bf[nt]);
        }

        // write S scores to smem
        float* sS = sm + AS_ST;
#pragma unroll
        for (int mt = 0; mt < 2; mt++) {
            int r0 = wms + mt * 16 + lg;
#pragma unroll
            for (int nt = 0; nt < 2; nt++) {
                int c0 = wns + nt * 8 + 2 * lc;
                *(float2*)(sS + r0 * 68 + c0) =
                    make_float2(sacc[mt][nt][0], sacc[mt][nt][1]);
                *(float2*)(sS + (r0 + 8) * 68 + c0) =
                    make_float2(sacc[mt][nt][2], sacc[mt][nt][3]);
            }
        }
        __syncthreads();

        // ---- online softmax (4 threads per row) ----
        {
            int row = tid >> 2;
            int q4  = tid & 3;
            float v[16];
            *(float4*)(v)      = *(const float4*)(sS + row * 68 + q4 * 16);
            *(float4*)(v + 4)  = *(const float4*)(sS + row * 68 + q4 * 16 + 4);
            *(float4*)(v + 8)  = *(const float4*)(sS + row * 68 + q4 * 16 + 8);
            *(float4*)(v + 12) = *(const float4*)(sS + row * 68 + q4 * 16 + 12);
            if (j == qt) {
#pragma unroll
                for (int i = 0; i < 16; i++)
                    if (q4 * 16 + i > row) v[i] = -1e30f;
            }
            float mo = sm[AST_M + row];
            float mx = v[0];
#pragma unroll
            for (int i = 1; i < 16; i++) mx = fmaxf(mx, v[i]);
            mx = fmaxf(mx, __shfl_xor_sync(0xffffffffu, mx, 1));
            mx = fmaxf(mx, __shfl_xor_sync(0xffffffffu, mx, 2));
            float mnew = fmaxf(mo, mx);
            float sum = 0.f;
            unsigned pv[16];
#pragma unroll
            for (int i = 0; i < 16; i++) {
                float p = __expf(v[i] - mnew);
                sum += p;
                pv[i] = f2tf(p);
            }
            sum += __shfl_xor_sync(0xffffffffu, sum, 1);
            sum += __shfl_xor_sync(0xffffffffu, sum, 2);
            unsigned* sP = (unsigned*)sS;
            *(uint4*)(sP + row * 68 + q4 * 16)      = *(uint4*)(pv);
            *(uint4*)(sP + row * 68 + q4 * 16 + 4)  = *(uint4*)(pv + 4);
            *(uint4*)(sP + row * 68 + q4 * 16 + 8)  = *(uint4*)(pv + 8);
            *(uint4*)(sP + row * 68 + q4 * 16 + 12) = *(uint4*)(pv + 12);
            if (q4 == 0) {
                float esc = __expf(mo - mnew);
                sm[AST_M + row] = mnew;
                sm[AST_L + row] = sm[AST_L + row] * esc + sum;
                sm[AST_S + row] = esc;
            }
        }
        __syncthreads();

        // ---- rescale O, then O += P V (tf32 MMA) ----
#pragma unroll
        for (int mt = 0; mt < 2; mt++) {
            float e0 = sm[AST_S + wmp + mt * 16 + lg];
            float e1 = sm[AST_S + wmp + mt * 16 + lg + 8];
#pragma unroll
            for (int nt = 0; nt < 4; nt++) {
                oacc[mt][nt][0] *= e0;
                oacc[mt][nt][1] *= e0;
                oacc[mt][nt][2] *= e1;
                oacc[mt][nt][3] *= e1;
            }
        }
        const unsigned* sP = (const unsigned*)(sm + AS_ST);
        const float* Vs = sm + AV_ST + buf * 8704;
#pragma unroll
        for (int ks = 0; ks < 8; ks++) {
            unsigned af[2][4], bf2[4][2];
#pragma unroll
            for (int mt = 0; mt < 2; mt++) {
                int rm = wmp + mt * 16 + lg;
                af[mt][0] = sP[rm * 68 + ks * 8 + lc];
                af[mt][1] = sP[(rm + 8) * 68 + ks * 8 + lc];
                af[mt][2] = sP[rm * 68 + ks * 8 + lc + 4];
                af[mt][3] = sP[(rm + 8) * 68 + ks * 8 + lc + 4];
            }
#pragma unroll
            for (int nt = 0; nt < 4; nt++) {
                int cn = wnp + nt * 8 + lg;
                bf2[nt][0] = f2tf(Vs[(ks * 8 + lc) * 136 + cn]);
                bf2[nt][1] = f2tf(Vs[(ks * 8 + lc + 4) * 136 + cn]);
            }
#pragma unroll
            for (int mt = 0; mt < 2; mt++)
#pragma unroll
                for (int nt = 0; nt < 4; nt++)
                    mma_tf32(oacc[mt][nt], af[mt], bf2[nt]);
        }
        buf ^= 1;
    }

    // ---- epilogue: divide by l, write g_O ----
#pragma unroll
    for (int mt = 0; mt < 2; mt++) {
        int r  = wmp + mt * 16 + lg;
        float il0 = 1.0f / sm[AST_L + r];
        float il1 = 1.0f / sm[AST_L + r + 8];
        int gr = qt * 64 + r;
#pragma unroll
        for (int nt = 0; nt < 4; nt++) {
            int col = h * HDM + wnp + nt * 8 + 2 * lc;
            *(float2*)(g_O + gr * DIMV + col) =
                make_float2(oacc[mt][nt][0] * il0, oacc[mt][nt][1] * il0);
            *(float2*)(g_O + (gr + 8) * DIMV + col) =
                make_float2(oacc[mt][nt][2] * il1, oacc[mt][nt][3] * il1);
        }
    }
}

// ============================================================
// launch
// ============================================================
extern "C" void kernel_launch(void* const* d_in, const int* in_sizes, int n_in,
                              void* d_out, int out_size)
{
    const float* query = (const float*)d_in[0];
    const float* key   = (const float*)d_in[1];
    const float* value = (const float*)d_in[2];
    const float* Wq    = (const float*)d_in[3];
    const float* bq    = (const float*)d_in[4];
    const float* Wk    = (const float*)d_in[5];
    const float* bk    = (const float*)d_in[6];
    const float* Wv    = (const float*)d_in[7];
    const float* bv    = (const float*)d_in[8];
    const float* Wo    = (const float*)d_in[9];
    const float* bo    = (const float*)d_in[10];
    float* out = (float*)d_out;

    gemm_q_kernel<<<dim3(16, 16), 256>>>(query, Wq, bq);
    gemm_kv_kernel<<<dim3(4, 16, 2), 256>>>(key, value, Wk, bk, Wv, bv);

    {
        const int total = S_LEN * (NQH + NKVH) * 64;
        rope_kernel<<<(total + 255) / 256, 256>>>();
    }

    cudaFuncSetAttribute((const void*)attn_kernel,
                         cudaFuncAttributeMaxDynamicSharedMemorySize, ATT_SMEM);
    attn_kernel<<<dim3(32, 16), 256, ATT_SMEM>>>();

    gemm_o_kernel<<<dim3(16, 16), 256>>>(Wo, bo, out);
}

// round 4
// speedup vs baseline: 2.8387x; 1.0786x over previous
#include <cuda_runtime.h>
#include <math.h>

#define S_LEN   2048
#define DIMV    2048
#define KVD     512
#define NQH     16
#define NKVH    4
#define HDM     128

// ---- scratch (no cudaMalloc allowed) ----
__device__ float g_Q[S_LEN * DIMV];
__device__ float g_K[S_LEN * KVD];
__device__ float g_V[S_LEN * KVD];
__device__ float g_O[S_LEN * DIMV];

// ============================================================
// common tf32 helpers
// ============================================================
__device__ __forceinline__ unsigned f2tf(float f) {
    unsigned u;
    asm("cvt.rna.tf32.f32 %0, %1;" : "=r"(u) : "f"(f));
    return u;
}

__device__ __forceinline__ void mma_tf32(float* c, const unsigned* a, const unsigned* b) {
    asm volatile(
        "mma.sync.aligned.m16n8k8.row.col.f32.tf32.tf32.f32 "
        "{%0,%1,%2,%3}, {%4,%5,%6,%7}, {%8,%9}, {%0,%1,%2,%3};"
        : "+f"(c[0]), "+f"(c[1]), "+f"(c[2]), "+f"(c[3])
        : "r"(a[0]), "r"(a[1]), "r"(a[2]), "r"(a[3]), "r"(b[0]), "r"(b[1]));
}

__device__ __forceinline__ void cp16(unsigned dst, const void* src) {
    asm volatile("cp.async.cg.shared.global [%0], [%1], 16;" :: "r"(dst), "l"(src));
}
__device__ __forceinline__ void cp_commit() {
    asm volatile("cp.async.commit_group;");
}
__device__ __forceinline__ void cp_wait0() {
    asm volatile("cp.async.wait_group 0;" ::: "memory");
}

// ============================================================
// Pipelined tf32 GEMM: C[m][n] = sum_k A[m][k]*B[n][k] + bias[n]
// BM=128, BN=256, BK=16, 3-stage cp.async, 256 thr / 8 warps,
// warp tile 64x64. Smem: row-major f32, row stride 20 words
// (stride%8==4 -> fragment LDS conflict-free for A and B patterns).
// K fixed at 2048.
// ============================================================
#define GW_STG 7680                 // words/stage: A 128*20 + B 256*20
#define G_SMEM (3 * GW_STG * 4)     // 92160 bytes

__device__ __forceinline__ void gemm256_body(
    const float* __restrict__ A, const float* __restrict__ B,
    const float* __restrict__ bias, float* __restrict__ C,
    int N, int bm, int bn)
{
    extern __shared__ float sm[];
    unsigned smem_base = (unsigned)__cvta_generic_to_shared(sm);
    const int tid  = threadIdx.x;
    const int lane = tid & 31;
    const int wid  = tid >> 5;
    const int lg   = lane >> 2;
    const int lc   = lane & 3;
    const int wm   = (wid >> 2) * 64;
    const int wn   = (wid & 3) * 64;
    const int K    = 2048;

    const int row4 = tid >> 2;          // 0..63
    const int kseg = (tid & 3) * 4;     // 0,4,8,12

    const float* Ag = A + (bm + row4) * K + kseg;
    const float* Bg = B + (bn + row4) * K + kseg;
    const unsigned aw = row4 * 20 + kseg;
    const unsigned bw = 2560 + row4 * 20 + kseg;

#define G_ISSUE(kt, s) do {                                      \
        unsigned as_ = smem_base + ((s) * GW_STG + aw) * 4;      \
        const float* ag_ = Ag + (kt) * 16;                       \
        cp16(as_,              ag_);                             \
        cp16(as_ + 64*20*4,    ag_ + 64*K);                      \
        unsigned bs_ = smem_base + ((s) * GW_STG + bw) * 4;      \
        const float* bg_ = Bg + (kt) * 16;                       \
        cp16(bs_,              bg_);                             \
        cp16(bs_ + 64*20*4,    bg_ + 64*K);                      \
        cp16(bs_ + 128*20*4,   bg_ + 128*K);                     \
        cp16(bs_ + 192*20*4,   bg_ + 192*K);                     \
        cp_commit(); } while (0)

    float acc[4][8][4];
#pragma unroll
    for (int mt = 0; mt < 4; mt++)
#pragma unroll
        for (int nt = 0; nt < 8; nt++)
#pragma unroll
            for (int c = 0; c < 4; c++) acc[mt][nt][c] = 0.f;

    G_ISSUE(0, 0);
    G_ISSUE(1, 1);

    const int nIter = K / 16;   // 128
    for (int kt = 0; kt < nIter; kt++) {
        asm volatile("cp.async.wait_group 1;" ::: "memory");
        __syncthreads();
        if (kt + 2 < nIter) {
            int s = (kt + 2) % 3;
            G_ISSUE(kt + 2, s);
        } else {
            cp_commit();   // empty group keeps wait_group(1) counting aligned
        }

        const float* As = sm + (kt % 3) * GW_STG;
        const float* Bs = As + 2560;
#pragma unroll
        for (int ks = 0; ks < 2; ks++) {
            const int k0 = ks * 8 + lc;
            unsigned af[4][4], bf[8][2];
#pragma unroll
            for (int mt = 0; mt < 4; mt++) {
                const float* p = As + (wm + mt * 16 + lg) * 20 + k0;
                af[mt][0] = f2tf(p[0]);
                af[mt][1] = f2tf(p[160]);   // +8 rows
                af[mt][2] = f2tf(p[4]);     // +4 k
                af[mt][3] = f2tf(p[164]);
            }
#pragma unroll
            for (int nt = 0; nt < 8; nt++) {
                const float* p = Bs + (wn + nt * 8 + lg) * 20 + k0;
                bf[nt][0] = f2tf(p[0]);
                bf[nt][1] = f2tf(p[4]);
            }
#pragma unroll
            for (int mt = 0; mt < 4; mt++)
#pragma unroll
                for (int nt = 0; nt < 8; nt++)
                    mma_tf32(acc[mt][nt], af[mt], bf[nt]);
        }
    }
#undef G_ISSUE

    // epilogue: c0,c1 at (row, 2lc), c2,c3 at (row+8, 2lc)
#pragma unroll
    for (int mt = 0; mt < 4; mt++) {
        int row = bm + wm + mt * 16 + lg;
#pragma unroll
        for (int nt = 0; nt < 8; nt++) {
            int col = bn + wn + nt * 8 + 2 * lc;
            float b0 = __ldg(bias + col);
            float b1 = __ldg(bias + col + 1);
            *(float2*)(C + row * N + col) =
                make_float2(acc[mt][nt][0] + b0, acc[mt][nt][1] + b1);
            *(float2*)(C + (row + 8) * N + col) =
                make_float2(acc[mt][nt][2] + b0, acc[mt][nt][3] + b1);
        }
    }
}

// fused Q/K/V projection: blocks 0..127 Q, 128..159 K, 160..191 V
__global__ void __launch_bounds__(256) proj_kernel(
    const float* __restrict__ query, const float* __restrict__ key,
    const float* __restrict__ value,
    const float* __restrict__ Wq, const float* __restrict__ bq,
    const float* __restrict__ Wk, const float* __restrict__ bk,
    const float* __restrict__ Wv, const float* __restrict__ bv)
{
    int b = blockIdx.x;
    const float *A, *B, *bi;
    float* C;
    int N, bm, bn;
    if (b < 128) {
        A = query; B = Wq; bi = bq; C = g_Q; N = DIMV;
        bm = (b >> 3) * 128; bn = (b & 7) * 256;
    } else if (b < 160) {
        int i = b - 128;
        A = key; B = Wk; bi = bk; C = g_K; N = KVD;
        bm = (i >> 1) * 128; bn = (i & 1) * 256;
    } else {
        int i = b - 160;
        A = value; B = Wv; bi = bv; C = g_V; N = KVD;
        bm = (i >> 1) * 128; bn = (i & 1) * 256;
    }
    gemm256_body(A, B, bi, C, N, bm, bn);
}

__global__ void __launch_bounds__(256) gemm_o_kernel(
    const float* __restrict__ Wo, const float* __restrict__ bo,
    float* __restrict__ out)
{
    int b = blockIdx.x;
    gemm256_body(g_O, Wo, bo, out, DIMV, (b >> 3) * 128, (b & 7) * 256);
}

// ============================================================
// RoPE
// ============================================================
__global__ void __launch_bounds__(256) rope_kernel()
{
    const int total = S_LEN * (NQH + NKVH) * 64;
    int idx = blockIdx.x * blockDim.x + threadIdx.x;
    if (idx >= total) return;
    int j  = idx & 63;
    int t  = idx >> 6;
    int hh = t % (NQH + NKVH);
    int s  = t / (NQH + NKVH);

    float inv = powf(10000.0f, -(float)(2 * j) * (1.0f / 128.0f));
    float ang = (float)s * inv;
    float sn, cs;
    sincosf(ang, &sn, &cs);

    float* base = (hh < NQH) ? (g_Q + s * DIMV + hh * HDM)
                             : (g_K + s * KVD + (hh - NQH) * HDM);
    float x1 = base[j];
    float x2 = base[j + 64];
    base[j]      = x1 * cs - x2 * sn;
    base[j + 64] = x2 * cs + x1 * sn;
}

// ============================================================
// Flash attention with tf32 MMA, causal GQA (unchanged from R3)
// ============================================================
#define AQ_ST 0
#define AK_ST 8448
#define AV_ST 25344
#define AS_ST 42752
#define AST_M 47104
#define AST_L 47168
#define AST_S 47232
#define A_TOT 47296
#define ATT_SMEM (A_TOT * 4)

__device__ __forceinline__ void attn_issue_kv(
    const float* Kb, const float* Vb, int j, int buf,
    unsigned smem_base, int tid)
{
    const float* Ksrc = Kb + (j * 64) * KVD;
    const float* Vsrc = Vb + (j * 64) * KVD;
    unsigned kb = smem_base + (AK_ST + buf * 8448) * 4;
    unsigned vb = smem_base + (AV_ST + buf * 8704) * 4;
#pragma unroll
    for (int i = 0; i < 8; i++) {
        int c   = tid + i * 256;
        int row = c >> 5;
        int q16 = c & 31;
        cp16(kb + (row * 132 + q16 * 4) * 4, Ksrc + row * KVD + q16 * 4);
        cp16(vb + (row * 136 + q16 * 4) * 4, Vsrc + row * KVD + q16 * 4);
    }
    cp_commit();
}

__global__ void __launch_bounds__(256) attn_kernel()
{
    extern __shared__ float sm[];
    unsigned smem_base = (unsigned)__cvta_generic_to_shared(sm);

    const int tid  = threadIdx.x;
    const int lane = tid & 31;
    const int wid  = tid >> 5;
    const int qt   = gridDim.x - 1 - blockIdx.x;
    const int h    = blockIdx.y;
    const int kvh  = h >> 2;
    const int lg   = lane >> 2;
    const int lc   = lane & 3;

    const int wms = (wid >> 2) * 32;
    const int wns = (wid & 3) * 16;
    const int wmp = (wid >> 2) * 32;
    const int wnp = (wid & 3) * 32;

    const float* Qb = g_Q + h * HDM;
    const float* Kb = g_K + kvh * HDM;
    const float* Vb = g_V + kvh * HDM;

    attn_issue_kv(Kb, Vb, 0, 0, smem_base, tid);

    const float scale = 0.08838834764831845f;
    unsigned* Qst = (unsigned*)(sm + AQ_ST);
#pragma unroll
    for (int i = 0; i < 8; i++) {
        int li  = tid + i * 256;
        int row = li >> 5;
        int c4  = li & 31;
        float4 v = *(const float4*)(Qb + (qt * 64 + row) * DIMV + c4 * 4);
        uint4 u;
        u.x = f2tf(v.x * scale); u.y = f2tf(v.y * scale);
        u.z = f2tf(v.z * scale); u.w = f2tf(v.w * scale);
        *(uint4*)(Qst + row * 132 + c4 * 4) = u;
    }
    if (tid < 64) { sm[AST_M + tid] = -1e30f; sm[AST_L + tid] = 0.f; }
    __syncthreads();

    unsigned qf[2][16][4];
#pragma unroll
    for (int mt = 0; mt < 2; mt++) {
        int rm = wms + mt * 16 + lg;
#pragma unroll
        for (int ks = 0; ks < 16; ks++) {
            qf[mt][ks][0] = Qst[rm * 132 + ks * 8 + lc];
            qf[mt][ks][1] = Qst[(rm + 8) * 132 + ks * 8 + lc];
            qf[mt][ks][2] = Qst[rm * 132 + ks * 8 + lc + 4];
            qf[mt][ks][3] = Qst[(rm + 8) * 132 + ks * 8 + lc + 4];
        }
    }

    float oacc[2][4][4];
#pragma unroll
    for (int mt = 0; mt < 2; mt++)
#pragma unroll
        for (int nt = 0; nt < 4; nt++)
#pragma unroll
            for (int c = 0; c < 4; c++) oacc[mt][nt][c] = 0.f;

    int buf = 0;
    for (int j = 0; j <= qt; j++) {
        cp_wait0();
        __syncthreads();
        if (j < qt) attn_issue_kv(Kb, Vb, j + 1, buf ^ 1, smem_base, tid);

        const float* Ks = sm + AK_ST + buf * 8448;
        float sacc[2][2][4];
#pragma unroll
        for (int mt = 0; mt < 2; mt++)
#pragma unroll
            for (int nt = 0; nt < 2; nt++)
#pragma unroll
                for (int c = 0; c < 4; c++) sacc[mt][nt][c] = 0.f;

#pragma unroll
        for (int ks = 0; ks < 16; ks++) {
            unsigned bf[2][2];
#pragma unroll
            for (int nt = 0; nt < 2; nt++) {
                int cn = wns + nt * 8 + lg;
                bf[nt][0] = f2tf(Ks[cn * 132 + ks * 8 + lc]);
                bf[nt][1] = f2tf(Ks[cn * 132 + ks * 8 + lc + 4]);
            }
#pragma unroll
            for (int mt = 0; mt < 2; mt++)
#pragma unroll
                for (int nt = 0; nt < 2; nt++)
                    mma_tf32(sacc[mt][nt], qf[mt][ks], bf[nt]);
        }

        float* sS = sm + AS_ST;
#pragma unroll
        for (int mt = 0; mt < 2; mt++) {
            int r0 = wms + mt * 16 + lg;
#pragma unroll
            for (int nt = 0; nt < 2; nt++) {
                int c0 = wns + nt * 8 + 2 * lc;
                *(float2*)(sS + r0 * 68 + c0) =
                    make_float2(sacc[mt][nt][0], sacc[mt][nt][1]);
                *(float2*)(sS + (r0 + 8) * 68 + c0) =
                    make_float2(sacc[mt][nt][2], sacc[mt][nt][3]);
            }
        }
        __syncthreads();

        {
            int row = tid >> 2;
            int q4  = tid & 3;
            float v[16];
            *(float4*)(v)      = *(const float4*)(sS + row * 68 + q4 * 16);
            *(float4*)(v + 4)  = *(const float4*)(sS + row * 68 + q4 * 16 + 4);
            *(float4*)(v + 8)  = *(const float4*)(sS + row * 68 + q4 * 16 + 8);
            *(float4*)(v + 12) = *(const float4*)(sS + row * 68 + q4 * 16 + 12);
            if (j == qt) {
#pragma unroll
                for (int i = 0; i < 16; i++)
                    if (q4 * 16 + i > row) v[i] = -1e30f;
            }
            float mo = sm[AST_M + row];
            float mx = v[0];
#pragma unroll
            for (int i = 1; i < 16; i++) mx = fmaxf(mx, v[i]);
            mx = fmaxf(mx, __shfl_xor_sync(0xffffffffu, mx, 1));
            mx = fmaxf(mx, __shfl_xor_sync(0xffffffffu, mx, 2));
            float mnew = fmaxf(mo, mx);
            float sum = 0.f;
            unsigned pv[16];
#pragma unroll
            for (int i = 0; i < 16; i++) {
                float p = __expf(v[i] - mnew);
                sum += p;
                pv[i] = f2tf(p);
            }
            sum += __shfl_xor_sync(0xffffffffu, sum, 1);
            sum += __shfl_xor_sync(0xffffffffu, sum, 2);
            unsigned* sP = (unsigned*)sS;
            *(uint4*)(sP + row * 68 + q4 * 16)      = *(uint4*)(pv);
            *(uint4*)(sP + row * 68 + q4 * 16 + 4)  = *(uint4*)(pv + 4);
            *(uint4*)(sP + row * 68 + q4 * 16 + 8)  = *(uint4*)(pv + 8);
            *(uint4*)(sP + row * 68 + q4 * 16 + 12) = *(uint4*)(pv + 12);
            if (q4 == 0) {
                float esc = __expf(mo - mnew);
                sm[AST_M + row] = mnew;
                sm[AST_L + row] = sm[AST_L + row] * esc + sum;
                sm[AST_S + row] = esc;
            }
        }
        __syncthreads();

#pragma unroll
        for (int mt = 0; mt < 2; mt++) {
            float e0 = sm[AST_S + wmp + mt * 16 + lg];
            float e1 = sm[AST_S + wmp + mt * 16 + lg + 8];
#pragma unroll
            for (int nt = 0; nt < 4; nt++) {
                oacc[mt][nt][0] *= e0;
                oacc[mt][nt][1] *= e0;
                oacc[mt][nt][2] *= e1;
                oacc[mt][nt][3] *= e1;
            }
        }
        const unsigned* sP = (const unsigned*)(sm + AS_ST);
        const float* Vs = sm + AV_ST + buf * 8704;
#pragma unroll
        for (int ks = 0; ks < 8; ks++) {
            unsigned af[2][4], bf2[4][2];
#pragma unroll
            for (int mt = 0; mt < 2; mt++) {
                int rm = wmp + mt * 16 + lg;
                af[mt][0] = sP[rm * 68 + ks * 8 + lc];
                af[mt][1] = sP[(rm + 8) * 68 + ks * 8 + lc];
                af[mt][2] = sP[rm * 68 + ks * 8 + lc + 4];
                af[mt][3] = sP[(rm + 8) * 68 + ks * 8 + lc + 4];
            }
#pragma unroll
            for (int nt = 0; nt < 4; nt++) {
                int cn = wnp + nt * 8 + lg;
                bf2[nt][0] = f2tf(Vs[(ks * 8 + lc) * 136 + cn]);
                bf2[nt][1] = f2tf(Vs[(ks * 8 + lc + 4) * 136 + cn]);
            }
#pragma unroll
            for (int mt = 0; mt < 2; mt++)
#pragma unroll
                for (int nt = 0; nt < 4; nt++)
                    mma_tf32(oacc[mt][nt], af[mt], bf2[nt]);
        }
        buf ^= 1;
    }

#pragma unroll
    for (int mt = 0; mt < 2; mt++) {
        int r  = wmp + mt * 16 + lg;
        float il0 = 1.0f / sm[AST_L + r];
        float il1 = 1.0f / sm[AST_L + r + 8];
        int gr = qt * 64 + r;
#pragma unroll
        for (int nt = 0; nt < 4; nt++) {
            int col = h * HDM + wnp + nt * 8 + 2 * lc;
            *(float2*)(g_O + gr * DIMV + col) =
                make_float2(oacc[mt][nt][0] * il0, oacc[mt][nt][1] * il0);
            *(float2*)(g_O + (gr + 8) * DIMV + col) =
                make_float2(oacc[mt][nt][2] * il1, oacc[mt][nt][3] * il1);
        }
    }
}

// ============================================================
// launch
// ============================================================
extern "C" void kernel_launch(void* const* d_in, const int* in_sizes, int n_in,
                              void* d_out, int out_size)
{
    const float* query = (const float*)d_in[0];
    const float* key   = (const float*)d_in[1];
    const float* value = (const float*)d_in[2];
    const float* Wq    = (const float*)d_in[3];
    const float* bq    = (const float*)d_in[4];
    const float* Wk    = (const float*)d_in[5];
    const float* bk    = (const float*)d_in[6];
    const float* Wv    = (const float*)d_in[7];
    const float* bv    = (const float*)d_in[8];
    const float* Wo    = (const float*)d_in[9];
    const float* bo    = (const float*)d_in[10];
    float* out = (float*)d_out;

    cudaFuncSetAttribute((const void*)proj_kernel,
                         cudaFuncAttributeMaxDynamicSharedMemorySize, G_SMEM);
    cudaFuncSetAttribute((const void*)gemm_o_kernel,
                         cudaFuncAttributeMaxDynamicSharedMemorySize, G_SMEM);
    cudaFuncSetAttribute((const void*)attn_kernel,
                         cudaFuncAttributeMaxDynamicSharedMemorySize, ATT_SMEM);

    proj_kernel<<<192, 256, G_SMEM>>>(query, key, value, Wq, bq, Wk, bk, Wv, bv);

    {
        const int total = S_LEN * (NQH + NKVH) * 64;
        rope_kernel<<<(total + 255) / 256, 256>>>();
    }

    attn_kernel<<<dim3(32, 16), 256, ATT_SMEM>>>();

    gemm_o_kernel<<<128, 256, G_SMEM>>>(Wo, bo, out);
}

// round 5
// speedup vs baseline: 3.2165x; 1.1331x over previous
#include <cuda_runtime.h>
#include <math.h>

#define S_LEN   2048
#define DIMV    2048
#define KVD     512
#define NQH     16
#define NKVH    4
#define HDM     128

// ---- scratch (no cudaMalloc allowed) ----
__device__ float g_Q[S_LEN * DIMV];
__device__ float g_K[S_LEN * KVD];
__device__ float g_V[S_LEN * KVD];
__device__ float g_O[S_LEN * DIMV];
// tf32-pre-rounded copies of inputs
__device__ float r_query[S_LEN * DIMV];
__device__ float r_key[S_LEN * DIMV];
__device__ float r_value[S_LEN * DIMV];
__device__ float r_Wq[DIMV * DIMV];
__device__ float r_Wk[KVD * DIMV];
__device__ float r_Wv[KVD * DIMV];
__device__ float r_Wo[DIMV * DIMV];

// ============================================================
// helpers
// ============================================================
__device__ __forceinline__ unsigned f2tf(float f) {
    unsigned u;
    asm("cvt.rna.tf32.f32 %0, %1;" : "=r"(u) : "f"(f));
    return u;
}
__device__ __forceinline__ float rnd_tf(float f) {
    return __uint_as_float(f2tf(f));
}

__device__ __forceinline__ void mma_tf32(float* c, const unsigned* a, const unsigned* b) {
    asm volatile(
        "mma.sync.aligned.m16n8k8.row.col.f32.tf32.tf32.f32 "
        "{%0,%1,%2,%3}, {%4,%5,%6,%7}, {%8,%9}, {%0,%1,%2,%3};"
        : "+f"(c[0]), "+f"(c[1]), "+f"(c[2]), "+f"(c[3])
        : "r"(a[0]), "r"(a[1]), "r"(a[2]), "r"(a[3]), "r"(b[0]), "r"(b[1]));
}

__device__ __forceinline__ void cp16(unsigned dst, const void* src) {
    asm volatile("cp.async.cg.shared.global [%0], [%1], 16;" :: "r"(dst), "l"(src));
}
__device__ __forceinline__ void cp_commit() {
    asm volatile("cp.async.commit_group;");
}
__device__ __forceinline__ void cp_wait0() {
    asm volatile("cp.async.wait_group 0;" ::: "memory");
}

// ============================================================
// pre-round inputs to tf32 grid (RNA), streaming float4
// ============================================================
__global__ void __launch_bounds__(256) round_tf32_kernel(
    const float4* __restrict__ src, float4* __restrict__ dst, int n4)
{
    int i = blockIdx.x * blockDim.x + threadIdx.x;
    if (i >= n4) return;
    float4 v = src[i];
    v.x = rnd_tf(v.x); v.y = rnd_tf(v.y);
    v.z = rnd_tf(v.z); v.w = rnd_tf(v.w);
    dst[i] = v;
}

// ============================================================
// Pipelined tf32 GEMM: C[m][n] = sum_k A[m][k]*B[n][k] + bias[n]
// BM=128, BN=256, BK=32, 3-stage cp.async, 256 thr / 8 warps,
// warp tile 64x64. Operands pre-rounded to tf32 grid -> no cvt
// in inner loop. Smem row stride 36 words (conflict-free frags).
// K fixed 2048.
// ============================================================
#define GK     2048
#define GSTR   36
#define GB_OFF (128 * GSTR)          // 4608 words
#define GW_STG (384 * GSTR)          // 13824 words/stage
#define G_SMEM (3 * GW_STG * 4)      // 165888 bytes

__device__ __forceinline__ void g_issue(
    const float* ag, const float* bg, unsigned as_, unsigned bs_)
{
#pragma unroll
    for (int i = 0; i < 4; i++)
        cp16(as_ + i * 32 * GSTR * 4, ag + i * 32 * GK);
#pragma unroll
    for (int i = 0; i < 8; i++)
        cp16(bs_ + i * 32 * GSTR * 4, bg + i * 32 * GK);
    cp_commit();
}

template <bool ROUND>
__device__ __forceinline__ void gemm256_body(
    const float* __restrict__ A, const float* __restrict__ B,
    const float* __restrict__ bias, float* __restrict__ C,
    int N, int bm, int bn)
{
    extern __shared__ float sm[];
    unsigned smem_base = (unsigned)__cvta_generic_to_shared(sm);
    const int tid  = threadIdx.x;
    const int lane = tid & 31;
    const int wid  = tid >> 5;
    const int lg   = lane >> 2;
    const int lc   = lane & 3;
    const int wm   = (wid >> 2) * 64;
    const int wn   = (wid & 3) * 64;

    const int rowb = tid >> 3;           // 0..31
    const int ck   = (tid & 7) * 4;      // k chunk offset (floats)

    const float* Ag = A + (bm + rowb) * GK + ck;
    const float* Bg = B + (bn + rowb) * GK + ck;
    const unsigned aw = (rowb * GSTR + ck) * 4;
    const unsigned bw = (GB_OFF + rowb * GSTR + ck) * 4;

    float acc[4][8][4];
#pragma unroll
    for (int mt = 0; mt < 4; mt++)
#pragma unroll
        for (int nt = 0; nt < 8; nt++)
#pragma unroll
            for (int c = 0; c < 4; c++) acc[mt][nt][c] = 0.f;

    g_issue(Ag,      Bg,      smem_base + aw,                smem_base + bw);
    g_issue(Ag + 32, Bg + 32, smem_base + GW_STG * 4 + aw,   smem_base + GW_STG * 4 + bw);

    const int nIter = GK / 32;   // 64
    for (int kt = 0; kt < nIter; kt++) {
        asm volatile("cp.async.wait_group 1;" ::: "memory");
        __syncthreads();
        if (kt + 2 < nIter) {
            int s = (kt + 2) % 3;
            g_issue(Ag + (kt + 2) * 32, Bg + (kt + 2) * 32,
                    smem_base + (s * GW_STG) * 4 + aw,
                    smem_base + (s * GW_STG) * 4 + bw);
        } else {
            cp_commit();   // keep wait_group(1) counting aligned
        }

        const float* As = sm + (kt % 3) * GW_STG;
        const float* Bs = As + GB_OFF;
#pragma unroll
        for (int ks = 0; ks < 4; ks++) {
            const int k0 = ks * 8 + lc;
            unsigned af[4][4], bf[8][2];
#pragma unroll
            for (int mt = 0; mt < 4; mt++) {
                const float* p = As + (wm + mt * 16 + lg) * GSTR + k0;
                af[mt][0] = __float_as_uint(p[0]);
                af[mt][1] = __float_as_uint(p[8 * GSTR]);
                af[mt][2] = __float_as_uint(p[4]);
                af[mt][3] = __float_as_uint(p[8 * GSTR + 4]);
            }
#pragma unroll
            for (int nt = 0; nt < 8; nt++) {
                const float* p = Bs + (wn + nt * 8 + lg) * GSTR + k0;
                bf[nt][0] = __float_as_uint(p[0]);
                bf[nt][1] = __float_as_uint(p[4]);
            }
#pragma unroll
            for (int mt = 0; mt < 4; mt++)
#pragma unroll
                for (int nt = 0; nt < 8; nt++)
                    mma_tf32(acc[mt][nt], af[mt], bf[nt]);
        }
    }

#pragma unroll
    for (int mt = 0; mt < 4; mt++) {
        int row = bm + wm + mt * 16 + lg;
#pragma unroll
        for (int nt = 0; nt < 8; nt++) {
            int col = bn + wn + nt * 8 + 2 * lc;
            float b0 = __ldg(bias + col);
            float b1 = __ldg(bias + col + 1);
            float o0 = acc[mt][nt][0] + b0, o1 = acc[mt][nt][1] + b1;
            float o2 = acc[mt][nt][2] + b0, o3 = acc[mt][nt][3] + b1;
            if (ROUND) {
                o0 = rnd_tf(o0); o1 = rnd_tf(o1);
                o2 = rnd_tf(o2); o3 = rnd_tf(o3);
            }
            *(float2*)(C + row * N + col)       = make_float2(o0, o1);
            *(float2*)(C + (row + 8) * N + col) = make_float2(o2, o3);
        }
    }
}

// fused Q/K/V projection: blocks 0..127 Q, 128..159 K, 160..191 V
__global__ void __launch_bounds__(256) proj_kernel(
    const float* __restrict__ bq, const float* __restrict__ bk,
    const float* __restrict__ bv)
{
    int b = blockIdx.x;
    const float *A, *B, *bi;
    float* C;
    int N, bm, bn;
    if (b < 128) {
        A = r_query; B = r_Wq; bi = bq; C = g_Q; N = DIMV;
        bm = (b >> 3) * 128; bn = (b & 7) * 256;
    } else if (b < 160) {
        int i = b - 128;
        A = r_key; B = r_Wk; bi = bk; C = g_K; N = KVD;
        bm = (i >> 1) * 128; bn = (i & 1) * 256;
    } else {
        int i = b - 160;
        A = r_value; B = r_Wv; bi = bv; C = g_V; N = KVD;
        bm = (i >> 1) * 128; bn = (i & 1) * 256;
    }
    gemm256_body<true>(A, B, bi, C, N, bm, bn);
}

__global__ void __launch_bounds__(256) gemm_o_kernel(
    const float* __restrict__ bo, float* __restrict__ out)
{
    int b = blockIdx.x;
    gemm256_body<false>(g_O, r_Wo, bo, out, DIMV, (b >> 3) * 128, (b & 7) * 256);
}

// ============================================================
// RoPE (rounds outputs to tf32 grid)
// ============================================================
__global__ void __launch_bounds__(256) rope_kernel()
{
    const int total = S_LEN * (NQH + NKVH) * 64;
    int idx = blockIdx.x * blockDim.x + threadIdx.x;
    if (idx >= total) return;
    int j  = idx & 63;
    int t  = idx >> 6;
    int hh = t % (NQH + NKVH);
    int s  = t / (NQH + NKVH);

    float inv = powf(10000.0f, -(float)(2 * j) * (1.0f / 128.0f));
    float ang = (float)s * inv;
    float sn, cs;
    sincosf(ang, &sn, &cs);

    float* base = (hh < NQH) ? (g_Q + s * DIMV + hh * HDM)
                             : (g_K + s * KVD + (hh - NQH) * HDM);
    float x1 = base[j];
    float x2 = base[j + 64];
    base[j]      = rnd_tf(x1 * cs - x2 * sn);
    base[j + 64] = rnd_tf(x2 * cs + x1 * sn);
}

// ============================================================
// Flash attention with tf32 MMA, causal GQA.
// K/V/Q/P all pre-rounded -> no cvt in fragment loads.
// ============================================================
#define AQ_ST 0
#define AK_ST 8448
#define AV_ST 25344
#define AS_ST 42752
#define AST_M 47104
#define AST_L 47168
#define AST_S 47232
#define A_TOT 47296
#define ATT_SMEM (A_TOT * 4)

__device__ __forceinline__ void attn_issue_kv(
    const float* Kb, const float* Vb, int j, int buf,
    unsigned smem_base, int tid)
{
    const float* Ksrc = Kb + (j * 64) * KVD;
    const float* Vsrc = Vb + (j * 64) * KVD;
    unsigned kb = smem_base + (AK_ST + buf * 8448) * 4;
    unsigned vb = smem_base + (AV_ST + buf * 8704) * 4;
#pragma unroll
    for (int i = 0; i < 8; i++) {
        int c   = tid + i * 256;
        int row = c >> 5;
        int q16 = c & 31;
        cp16(kb + (row * 132 + q16 * 4) * 4, Ksrc + row * KVD + q16 * 4);
        cp16(vb + (row * 136 + q16 * 4) * 4, Vsrc + row * KVD + q16 * 4);
    }
    cp_commit();
}

__global__ void __launch_bounds__(256) attn_kernel()
{
    extern __shared__ float sm[];
    unsigned smem_base = (unsigned)__cvta_generic_to_shared(sm);

    const int tid  = threadIdx.x;
    const int lane = tid & 31;
    const int wid  = tid >> 5;
    const int qt   = gridDim.x - 1 - blockIdx.x;
    const int h    = blockIdx.y;
    const int kvh  = h >> 2;
    const int lg   = lane >> 2;
    const int lc   = lane & 3;

    const int wms = (wid >> 2) * 32;
    const int wns = (wid & 3) * 16;
    const int wmp = (wid >> 2) * 32;
    const int wnp = (wid & 3) * 32;

    const float* Qb = g_Q + h * HDM;
    const float* Kb = g_K + kvh * HDM;
    const float* Vb = g_V + kvh * HDM;

    attn_issue_kv(Kb, Vb, 0, 0, smem_base, tid);

    const float scale = 0.08838834764831845f;
    unsigned* Qst = (unsigned*)(sm + AQ_ST);
#pragma unroll
    for (int i = 0; i < 8; i++) {
        int li  = tid + i * 256;
        int row = li >> 5;
        int c4  = li & 31;
        float4 v = *(const float4*)(Qb + (qt * 64 + row) * DIMV + c4 * 4);
        uint4 u;
        u.x = f2tf(v.x * scale); u.y = f2tf(v.y * scale);
        u.z = f2tf(v.z * scale); u.w = f2tf(v.w * scale);
        *(uint4*)(Qst + row * 132 + c4 * 4) = u;
    }
    if (tid < 64) { sm[AST_M + tid] = -1e30f; sm[AST_L + tid] = 0.f; }
    __syncthreads();

    unsigned qf[2][16][4];
#pragma unroll
    for (int mt = 0; mt < 2; mt++) {
        int rm = wms + mt * 16 + lg;
#pragma unroll
        for (int ks = 0; ks < 16; ks++) {
            qf[mt][ks][0] = Qst[rm * 132 + ks * 8 + lc];
            qf[mt][ks][1] = Qst[(rm + 8) * 132 + ks * 8 + lc];
            qf[mt][ks][2] = Qst[rm * 132 + ks * 8 + lc + 4];
            qf[mt][ks][3] = Qst[(rm + 8) * 132 + ks * 8 + lc + 4];
        }
    }

    float oacc[2][4][4];
#pragma unroll
    for (int mt = 0; mt < 2; mt++)
#pragma unroll
        for (int nt = 0; nt < 4; nt++)
#pragma unroll
            for (int c = 0; c < 4; c++) oacc[mt][nt][c] = 0.f;

    int buf = 0;
    for (int j = 0; j <= qt; j++) {
        cp_wait0();
        __syncthreads();
        if (j < qt) attn_issue_kv(Kb, Vb, j + 1, buf ^ 1, smem_base, tid);

        const unsigned* Ks = (const unsigned*)(sm + AK_ST + buf * 8448);
        float sacc[2][2][4];
#pragma unroll
        for (int mt = 0; mt < 2; mt++)
#pragma unroll
            for (int nt = 0; nt < 2; nt++)
#pragma unroll
                for (int c = 0; c < 4; c++) sacc[mt][nt][c] = 0.f;

#pragma unroll
        for (int ks = 0; ks < 16; ks++) {
            unsigned bf[2][2];
#pragma unroll
            for (int nt = 0; nt < 2; nt++) {
                int cn = wns + nt * 8 + lg;
                bf[nt][0] = Ks[cn * 132 + ks * 8 + lc];
                bf[nt][1] = Ks[cn * 132 + ks * 8 + lc + 4];
            }
#pragma unroll
            for (int mt = 0; mt < 2; mt++)
#pragma unroll
                for (int nt = 0; nt < 2; nt++)
                    mma_tf32(sacc[mt][nt], qf[mt][ks], bf[nt]);
        }

        float* sS = sm + AS_ST;
#pragma unroll
        for (int mt = 0; mt < 2; mt++) {
            int r0 = wms + mt * 16 + lg;
#pragma unroll
            for (int nt = 0; nt < 2; nt++) {
                int c0 = wns + nt * 8 + 2 * lc;
                *(float2*)(sS + r0 * 68 + c0) =
                    make_float2(sacc[mt][nt][0], sacc[mt][nt][1]);
                *(float2*)(sS + (r0 + 8) * 68 + c0) =
                    make_float2(sacc[mt][nt][2], sacc[mt][nt][3]);
            }
        }
        __syncthreads();

        {
            int row = tid >> 2;
            int q4  = tid & 3;
            float v[16];
            *(float4*)(v)      = *(const float4*)(sS + row * 68 + q4 * 16);
            *(float4*)(v + 4)  = *(const float4*)(sS + row * 68 + q4 * 16 + 4);
            *(float4*)(v + 8)  = *(const float4*)(sS + row * 68 + q4 * 16 + 8);
            *(float4*)(v + 12) = *(const float4*)(sS + row * 68 + q4 * 16 + 12);
            if (j == qt) {
#pragma unroll
                for (int i = 0; i < 16; i++)
                    if (q4 * 16 + i > row) v[i] = -1e30f;
            }
            float mo = sm[AST_M + row];
            float mx = v[0];
#pragma unroll
            for (int i = 1; i < 16; i++) mx = fmaxf(mx, v[i]);
            mx = fmaxf(mx, __shfl_xor_sync(0xffffffffu, mx, 1));
            mx = fmaxf(mx, __shfl_xor_sync(0xffffffffu, mx, 2));
            float mnew = fmaxf(mo, mx);
            float sum = 0.f;
            unsigned pv[16];
#pragma unroll
            for (int i = 0; i < 16; i++) {
                float p = __expf(v[i] - mnew);
                sum += p;
                pv[i] = f2tf(p);
            }
            sum += __shfl_xor_sync(0xffffffffu, sum, 1);
            sum += __shfl_xor_sync(0xffffffffu, sum, 2);
            unsigned* sP = (unsigned*)sS;
            *(uint4*)(sP + row * 68 + q4 * 16)      = *(uint4*)(pv);
            *(uint4*)(sP + row * 68 + q4 * 16 + 4)  = *(uint4*)(pv + 4);
            *(uint4*)(sP + row * 68 + q4 * 16 + 8)  = *(uint4*)(pv + 8);
            *(uint4*)(sP + row * 68 + q4 * 16 + 12) = *(uint4*)(pv + 12);
            if (q4 == 0) {
                float esc = __expf(mo - mnew);
                sm[AST_M + row] = mnew;
                sm[AST_L + row] = sm[AST_L + row] * esc + sum;
                sm[AST_S + row] = esc;
            }
        }
        __syncthreads();

#pragma unroll
        for (int mt = 0; mt < 2; mt++) {
            float e0 = sm[AST_S + wmp + mt * 16 + lg];
            float e1 = sm[AST_S + wmp + mt * 16 + lg + 8];
#pragma unroll
            for (int nt = 0; nt < 4; nt++) {
                oacc[mt][nt][0] *= e0;
                oacc[mt][nt][1] *= e0;
                oacc[mt][nt][2] *= e1;
                oacc[mt][nt][3] *= e1;
            }
        }
        const unsigned* sP = (const unsigned*)(sm + AS_ST);
        const unsigned* Vs = (const unsigned*)(sm + AV_ST + buf * 8704);
#pragma unroll
        for (int ks = 0; ks < 8; ks++) {
            unsigned af[2][4], bf2[4][2];
#pragma unroll
            for (int mt = 0; mt < 2; mt++) {
                int rm = wmp + mt * 16 + lg;
                af[mt][0] = sP[rm * 68 + ks * 8 + lc];
                af[mt][1] = sP[(rm + 8) * 68 + ks * 8 + lc];
                af[mt][2] = sP[rm * 68 + ks * 8 + lc + 4];
                af[mt][3] = sP[(rm + 8) * 68 + ks * 8 + lc + 4];
            }
#pragma unroll
            for (int nt = 0; nt < 4; nt++) {
                int cn = wnp + nt * 8 + lg;
                bf2[nt][0] = Vs[(ks * 8 + lc) * 136 + cn];
                bf2[nt][1] = Vs[(ks * 8 + lc + 4) * 136 + cn];
            }
#pragma unroll
            for (int mt = 0; mt < 2; mt++)
#pragma unroll
                for (int nt = 0; nt < 4; nt++)
                    mma_tf32(oacc[mt][nt], af[mt], bf2[nt]);
        }
        buf ^= 1;
    }

    // epilogue: divide by l, round to tf32 grid (g_O feeds gemm_o MMA)
#pragma unroll
    for (int mt = 0; mt < 2; mt++) {
        int r  = wmp + mt * 16 + lg;
        float il0 = 1.0f / sm[AST_L + r];
        float il1 = 1.0f / sm[AST_L + r + 8];
        int gr = qt * 64 + r;
#pragma unroll
        for (int nt = 0; nt < 4; nt++) {
            int col = h * HDM + wnp + nt * 8 + 2 * lc;
            *(float2*)(g_O + gr * DIMV + col) =
                make_float2(rnd_tf(oacc[mt][nt][0] * il0), rnd_tf(oacc[mt][nt][1] * il0));
            *(float2*)(g_O + (gr + 8) * DIMV + col) =
                make_float2(rnd_tf(oacc[mt][nt][2] * il1), rnd_tf(oacc[mt][nt][3] * il1));
        }
    }
}

// ============================================================
// launch
// ============================================================
extern "C" void kernel_launch(void* const* d_in, const int* in_sizes, int n_in,
                              void* d_out, int out_size)
{
    const float* query = (const float*)d_in[0];
    const float* key   = (const float*)d_in[1];
    const float* value = (const float*)d_in[2];
    const float* Wq    = (const float*)d_in[3];
    const float* bq    = (const float*)d_in[4];
    const float* Wk    = (const float*)d_in[5];
    const float* bk    = (const float*)d_in[6];
    const float* Wv    = (const float*)d_in[7];
    const float* bv    = (const float*)d_in[8];
    const float* Wo    = (const float*)d_in[9];
    const float* bo    = (const float*)d_in[10];
    float* out = (float*)d_out;

    cudaFuncSetAttribute((const void*)proj_kernel,
                         cudaFuncAttributeMaxDynamicSharedMemorySize, G_SMEM);
    cudaFuncSetAttribute((const void*)gemm_o_kernel,
                         cudaFuncAttributeMaxDynamicSharedMemorySize, G_SMEM);
    cudaFuncSetAttribute((const void*)attn_kernel,
                         cudaFuncAttributeMaxDynamicSharedMemorySize, ATT_SMEM);

    // pre-round inputs to tf32 grid
    float* rq; cudaGetSymbolAddress((void**)&rq, r_query);
    float* rk; cudaGetSymbolAddress((void**)&rk, r_key);
    float* rv; cudaGetSymbolAddress((void**)&rv, r_value);
    float* rwq; cudaGetSymbolAddress((void**)&rwq, r_Wq);
    float* rwk; cudaGetSymbolAddress((void**)&rwk, r_Wk);
    float* rwv; cudaGetSymbolAddress((void**)&rwv, r_Wv);
    float* rwo; cudaGetSymbolAddress((void**)&rwo, r_Wo);

    const int n4_big = (S_LEN * DIMV) / 4;   // 1M float4
    const int n4_sm  = (KVD * DIMV) / 4;     // 256K float4
    round_tf32_kernel<<<(n4_big + 255) / 256, 256>>>((const float4*)query, (float4*)rq, n4_big);
    round_tf32_kernel<<<(n4_big + 255) / 256, 256>>>((const float4*)key,   (float4*)rk, n4_big);
    round_tf32_kernel<<<(n4_big + 255) / 256, 256>>>((const float4*)value, (float4*)rv, n4_big);
    round_tf32_kernel<<<(n4_big + 255) / 256, 256>>>((const float4*)Wq,    (float4*)rwq, n4_big);
    round_tf32_kernel<<<(n4_sm  + 255) / 256, 256>>>((const float4*)Wk,    (float4*)rwk, n4_sm);
    round_tf32_kernel<<<(n4_sm  + 255) / 256, 256>>>((const float4*)Wv,    (float4*)rwv, n4_sm);
    round_tf32_kernel<<<(n4_big + 255) / 256, 256>>>((const float4*)Wo,    (float4*)rwo, n4_big);

    proj_kernel<<<192, 256, G_SMEM>>>(bq, bk, bv);

    {
        const int total = S_LEN * (NQH + NKVH) * 64;
        rope_kernel<<<(total + 255) / 256, 256>>>();
    }

    attn_kernel<<<dim3(32, 16), 256, ATT_SMEM>>>();

    gemm_o_kernel<<<128, 256, G_SMEM>>>(bo, out);
}

// round 7
// speedup vs baseline: 5.3313x; 1.6575x over previous
#include <cuda_runtime.h>
#include <cuda_fp16.h>
#include <math.h>

#define S_LEN   2048
#define DIMV    2048
#define KVD     512
#define NQH     16
#define NKVH    4
#define HDM     128

// ---- scratch (no cudaMalloc allowed) ----
__device__ __half h_query[S_LEN * DIMV];
__device__ __half h_key[S_LEN * DIMV];
__device__ __half h_value[S_LEN * DIMV];
__device__ __half h_Wq[DIMV * DIMV];
__device__ __half h_Wk[KVD * DIMV];
__device__ __half h_Wv[KVD * DIMV];
__device__ __half h_Wo[DIMV * DIMV];
__device__ __half g_Qh[S_LEN * DIMV];
__device__ __half g_Kh[S_LEN * KVD];
__device__ __half g_Vh[S_LEN * KVD];
__device__ __half g_Oh[S_LEN * DIMV];

// ============================================================
// helpers
// ============================================================
__device__ __forceinline__ void mma_f16(float* c, const unsigned* a, const unsigned* b) {
    asm volatile(
        "mma.sync.aligned.m16n8k16.row.col.f32.f16.f16.f32 "
        "{%0,%1,%2,%3}, {%4,%5,%6,%7}, {%8,%9}, {%0,%1,%2,%3};"
        : "+f"(c[0]), "+f"(c[1]), "+f"(c[2]), "+f"(c[3])
        : "r"(a[0]), "r"(a[1]), "r"(a[2]), "r"(a[3]), "r"(b[0]), "r"(b[1]));
}

__device__ __forceinline__ void ldsm_x4_t(
    unsigned& r0, unsigned& r1, unsigned& r2, unsigned& r3, unsigned addr)
{
    asm volatile("ldmatrix.sync.aligned.m8n8.x4.trans.shared.b16 {%0,%1,%2,%3}, [%4];"
        : "=r"(r0), "=r"(r1), "=r"(r2), "=r"(r3) : "r"(addr));
}

__device__ __forceinline__ void cp16(unsigned dst, const void* src) {
    asm volatile("cp.async.cg.shared.global [%0], [%1], 16;" :: "r"(dst), "l"(src));
}
__device__ __forceinline__ void cp_commit() {
    asm volatile("cp.async.commit_group;");
}
__device__ __forceinline__ void cp_wait0() {
    asm volatile("cp.async.wait_group 0;" ::: "memory");
}

// ============================================================
// fp32 -> fp16 convert (streaming)
// ============================================================
__global__ void __launch_bounds__(256) cvt_half_kernel(
    const float4* __restrict__ src, __half2* __restrict__ dst, int n4)
{
    int i = blockIdx.x * blockDim.x + threadIdx.x;
    if (i >= n4) return;
    float4 v = src[i];
    dst[2 * i]     = __floats2half2_rn(v.x, v.y);
    dst[2 * i + 1] = __floats2half2_rn(v.z, v.w);
}

// ============================================================
// fp16 GEMM: C[m][n] = sum_k A[m][k]*B[n][k] + bias[n]
// BM=128, BN=256, BK=64 halves, 3-stage cp.async, 256thr/8 warps,
// warp tile 64x64, mma.m16n8k16. Smem half rows stride 72 halves
// (36 words == 4 mod 32 -> conflict-free fragment LDS).
// K fixed 2048.
// ============================================================
#define GKH    2048
#define HSTR   72                  // halves per smem row
#define WSTR   36                  // words per smem row
#define GA_B   18432               // A region bytes (128*72*2)
#define GSTG_B 55296               // stage bytes (A + 256*72*2)
#define G_SMEM (3 * GSTG_B)        // 165888

__device__ __forceinline__ void g_issue_h(
    const __half* ag, const __half* bg, unsigned as_, unsigned bs_)
{
#pragma unroll
    for (int i = 0; i < 4; i++)
        cp16(as_ + i * 32 * HSTR * 2, ag + i * 32 * GKH);
#pragma unroll
    for (int i = 0; i < 8; i++)
        cp16(bs_ + i * 32 * HSTR * 2, bg + i * 32 * GKH);
    cp_commit();
}

template <bool HALF_OUT>
__device__ __forceinline__ void gemm_f16_body(
    const __half* __restrict__ A, const __half* __restrict__ B,
    const float* __restrict__ bias, void* __restrict__ Cv,
    int N, int bm, int bn)
{
    extern __shared__ char smc[];
    unsigned smem_base = (unsigned)__cvta_generic_to_shared(smc);
    const int tid  = threadIdx.x;
    const int lane = tid & 31;
    const int wid  = tid >> 5;
    const int lg   = lane >> 2;
    const int lc   = lane & 3;
    const int wm   = (wid >> 2) * 64;
    const int wn   = (wid & 3) * 64;

    const int rowb = tid >> 3;          // 0..31
    const int seg  = tid & 7;           // 16B segment (8 halves)

    const __half* Ag = A + (bm + rowb) * GKH + seg * 8;
    const __half* Bg = B + (bn + rowb) * GKH + seg * 8;
    const unsigned aoff = (rowb * HSTR + seg * 8) * 2;
    const unsigned boff = GA_B + (rowb * HSTR + seg * 8) * 2;

    float acc[4][8][4];
#pragma unroll
    for (int mt = 0; mt < 4; mt++)
#pragma unroll
        for (int nt = 0; nt < 8; nt++)
#pragma unroll
            for (int c = 0; c < 4; c++) acc[mt][nt][c] = 0.f;

    g_issue_h(Ag,      Bg,      smem_base + aoff,          smem_base + boff);
    g_issue_h(Ag + 64, Bg + 64, smem_base + GSTG_B + aoff, smem_base + GSTG_B + boff);

    const int nIter = GKH / 64;   // 32
    for (int kt = 0; kt < nIter; kt++) {
        asm volatile("cp.async.wait_group 1;" ::: "memory");
        __syncthreads();
        if (kt + 2 < nIter) {
            int s = (kt + 2) % 3;
            g_issue_h(Ag + (kt + 2) * 64, Bg + (kt + 2) * 64,
                      smem_base + s * GSTG_B + aoff,
                      smem_base + s * GSTG_B + boff);
        } else {
            cp_commit();
        }

        const unsigned* As = (const unsigned*)(smc + (kt % 3) * GSTG_B);
        const unsigned* Bs = As + GA_B / 4;
#pragma unroll
        for (int ks = 0; ks < 4; ks++) {
            unsigned af[4][4], bf[8][2];
#pragma unroll
            for (int mt = 0; mt < 4; mt++) {
                int base = (wm + mt * 16 + lg) * WSTR + ks * 8 + lc;
                af[mt][0] = As[base];
                af[mt][1] = As[base + 8 * WSTR];
                af[mt][2] = As[base + 4];
                af[mt][3] = As[base + 8 * WSTR + 4];
            }
#pragma unroll
            for (int nt = 0; nt < 8; nt++) {
                int nb = (wn + nt * 8 + lg) * WSTR + ks * 8 + lc;
                bf[nt][0] = Bs[nb];
                bf[nt][1] = Bs[nb + 4];
            }
#pragma unroll
            for (int mt = 0; mt < 4; mt++)
#pragma unroll
                for (int nt = 0; nt < 8; nt++)
                    mma_f16(acc[mt][nt], af[mt], bf[nt]);
        }
    }

#pragma unroll
    for (int mt = 0; mt < 4; mt++) {
        int row = bm + wm + mt * 16 + lg;
#pragma unroll
        for (int nt = 0; nt < 8; nt++) {
            int col = bn + wn + nt * 8 + 2 * lc;
            float b0 = __ldg(bias + col);
            float b1 = __ldg(bias + col + 1);
            float o0 = acc[mt][nt][0] + b0, o1 = acc[mt][nt][1] + b1;
            float o2 = acc[mt][nt][2] + b0, o3 = acc[mt][nt][3] + b1;
            if (HALF_OUT) {
                __half* C = (__half*)Cv;
                *(__half2*)(C + row * N + col)       = __floats2half2_rn(o0, o1);
                *(__half2*)(C + (row + 8) * N + col) = __floats2half2_rn(o2, o3);
            } else {
                float* C = (float*)Cv;
                *(float2*)(C + row * N + col)       = make_float2(o0, o1);
                *(float2*)(C + (row + 8) * N + col) = make_float2(o2, o3);
            }
        }
    }
}

// fused Q/K/V projection: blocks 0..127 Q, 128..159 K, 160..191 V
__global__ void __launch_bounds__(256) proj_kernel(
    const float* __restrict__ bq, const float* __restrict__ bk,
    const float* __restrict__ bv)
{
    int b = blockIdx.x;
    const __half *A, *B;
    const float* bi;
    __half* C;
    int N, bm, bn;
    if (b < 128) {
        A = h_query; B = h_Wq; bi = bq; C = g_Qh; N = DIMV;
        bm = (b >> 3) * 128; bn = (b & 7) * 256;
    } else if (b < 160) {
        int i = b - 128;
        A = h_key; B = h_Wk; bi = bk; C = g_Kh; N = KVD;
        bm = (i >> 1) * 128; bn = (i & 1) * 256;
    } else {
        int i = b - 160;
        A = h_value; B = h_Wv; bi = bv; C = g_Vh; N = KVD;
        bm = (i >> 1) * 128; bn = (i & 1) * 256;
    }
    gemm_f16_body<true>(A, B, bi, C, N, bm, bn);
}

__global__ void __launch_bounds__(256) gemm_o_kernel(
    const float* __restrict__ bo, float* __restrict__ out)
{
    int b = blockIdx.x;
    gemm_f16_body<false>(g_Oh, h_Wo, bo, out, DIMV, (b >> 3) * 128, (b & 7) * 256);
}

// ============================================================
// RoPE on half data
// ============================================================
__global__ void __launch_bounds__(256) rope_kernel()
{
    const int total = S_LEN * (NQH + NKVH) * 64;
    int idx = blockIdx.x * blockDim.x + threadIdx.x;
    if (idx >= total) return;
    int j  = idx & 63;
    int t  = idx >> 6;
    int hh = t % (NQH + NKVH);
    int s  = t / (NQH + NKVH);

    float inv = powf(10000.0f, -(float)(2 * j) * (1.0f / 128.0f));
    float ang = (float)s * inv;
    float sn, cs;
    sincosf(ang, &sn, &cs);

    __half* base = (hh < NQH) ? (g_Qh + s * DIMV + hh * HDM)
                              : (g_Kh + s * KVD + (hh - NQH) * HDM);
    float x1 = __half2float(base[j]);
    float x2 = __half2float(base[j + 64]);
    base[j]      = __float2half_rn(x1 * cs - x2 * sn);
    base[j + 64] = __float2half_rn(x2 * cs + x1 * sn);
}

// ============================================================
// Flash attention, fp16 MMA (m16n8k16), causal GQA.
// BM=BN=64, HD=128, 256 thr / 8 warps.
// Smem (bytes):
//   [0, 17408)      Q stage (64x136 half) -- reused as sS f32 [64][68]
//   [17408, 52224)  K 2x (64x136 half)
//   [52224, 87040)  V 2x (64x136 half)
//   [87040, 96256)  sP half [64][72]
//   [96256, 97024)  stats m/l/esc (64 f32 each)
// ============================================================
#define AQ_B   0
#define AK_B   17408
#define AV_B   52224
#define ASP_B  87040
#define AM_B   96256
#define AL_B   96512
#define AS_B   96768
#define ATT_SMEM 97024
#define KVSTR  136      // halves per K/V smem row
#define KVW    68       // words per K/V (and Q) smem row
#define PSW    36       // words per sP row

__device__ __forceinline__ void attn_issue_kv(
    const __half* Kb, const __half* Vb, int j, int buf,
    unsigned smem_base, int tid)
{
    const __half* Ksrc = Kb + (j * 64) * KVD;
    const __half* Vsrc = Vb + (j * 64) * KVD;
    unsigned kb = smem_base + AK_B + buf * 17408;
    unsigned vb = smem_base + AV_B + buf * 17408;
#pragma unroll
    for (int i = 0; i < 4; i++) {
        int c   = tid + i * 256;       // 0..1023
        int row = c >> 4;
        int sg  = c & 15;
        cp16(kb + (row * KVSTR + sg * 8) * 2, Ksrc + row * KVD + sg * 8);
        cp16(vb + (row * KVSTR + sg * 8) * 2, Vsrc + row * KVD + sg * 8);
    }
    cp_commit();
}

__global__ void __launch_bounds__(256) attn_kernel()
{
    extern __shared__ char smc[];
    unsigned smem_base = (unsigned)__cvta_generic_to_shared(smc);
    float* sm = (float*)smc;

    const int tid  = threadIdx.x;
    const int lane = tid & 31;
    const int wid  = tid >> 5;
    const int qt   = gridDim.x - 1 - blockIdx.x;   // heavy blocks first
    const int h    = blockIdx.y;
    const int kvh  = h >> 2;
    const int lg   = lane >> 2;
    const int lc   = lane & 3;

    const int wms = (wid >> 2) * 32;   // S warp tile 32x16
    const int wns = (wid & 3) * 16;
    const int wmp = (wid >> 2) * 32;   // PV warp tile 32x32
    const int wnp = (wid & 3) * 32;

    const __half* Qb = g_Qh + h * HDM;
    const __half* Kb = g_Kh + kvh * HDM;
    const __half* Vb = g_Vh + kvh * HDM;

    attn_issue_kv(Kb, Vb, 0, 0, smem_base, tid);

    // stage Q (cp.async, raw half)
    {
        const __half* Qsrc = Qb + (qt * 64) * DIMV;
#pragma unroll
        for (int i = 0; i < 4; i++) {
            int c   = tid + i * 256;
            int row = c >> 4;
            int sg  = c & 15;
            cp16(smem_base + AQ_B + (row * KVSTR + sg * 8) * 2,
                 Qsrc + row * DIMV + sg * 8);
        }
        cp_commit();
    }
    {
        float* mrow = (float*)(smc + AM_B);
        float* lrow = (float*)(smc + AL_B);
        if (tid < 64) { mrow[tid] = -1e30f; lrow[tid] = 0.f; }
    }
    cp_wait0();
    __syncthreads();

    // extract Q fragments -> registers
    unsigned qf[2][8][4];
    {
        const unsigned* Qw = (const unsigned*)(smc + AQ_B);
#pragma unroll
        for (int mt = 0; mt < 2; mt++) {
            int rb = (wms + mt * 16 + lg) * KVW;
#pragma unroll
            for (int ks = 0; ks < 8; ks++) {
                int base = rb + ks * 8 + lc;
                qf[mt][ks][0] = Qw[base];
                qf[mt][ks][1] = Qw[base + 8 * KVW];
                qf[mt][ks][2] = Qw[base + 4];
                qf[mt][ks][3] = Qw[base + 8 * KVW + 4];
            }
        }
    }
    __syncthreads();   // Q region may now be reused as sS

    float oacc[2][4][4];
#pragma unroll
    for (int mt = 0; mt < 2; mt++)
#pragma unroll
        for (int nt = 0; nt < 4; nt++)
#pragma unroll
            for (int c = 0; c < 4; c++) oacc[mt][nt][c] = 0.f;

    const float scale = 0.08838834764831845f;   // 1/sqrt(128)
    int buf = 0;
    for (int j = 0; j <= qt; j++) {
        if (j < qt) attn_issue_kv(Kb, Vb, j + 1, buf ^ 1, smem_base, tid);

        // ---- S = Q K^T ----
        const unsigned* Ksw = (const unsigned*)(smc + AK_B + buf * 17408);
        float sacc[2][2][4];
#pragma unroll
        for (int mt = 0; mt < 2; mt++)
#pragma unroll
            for (int nt = 0; nt < 2; nt++)
#pragma unroll
                for (int c = 0; c < 4; c++) sacc[mt][nt][c] = 0.f;

#pragma unroll
        for (int ks = 0; ks < 8; ks++) {
            unsigned bf[2][2];
#pragma unroll
            for (int nt = 0; nt < 2; nt++) {
                int nb = (wns + nt * 8 + lg) * KVW + ks * 8 + lc;
                bf[nt][0] = Ksw[nb];
                bf[nt][1] = Ksw[nb + 4];
            }
#pragma unroll
            for (int mt = 0; mt < 2; mt++)
#pragma unroll
                for (int nt = 0; nt < 2; nt++)
                    mma_f16(sacc[mt][nt], qf[mt][ks], bf[nt]);
        }

        float* sS = sm;   // overlaps retired Q stage
#pragma unroll
        for (int mt = 0; mt < 2; mt++) {
            int r0 = wms + mt * 16 + lg;
#pragma unroll
            for (int nt = 0; nt < 2; nt++) {
                int c0 = wns + nt * 8 + 2 * lc;
                *(float2*)(sS + r0 * 68 + c0) =
                    make_float2(sacc[mt][nt][0], sacc[mt][nt][1]);
                *(float2*)(sS + (r0 + 8) * 68 + c0) =
                    make_float2(sacc[mt][nt][2], sacc[mt][nt][3]);
            }
        }
        __syncthreads();

        // ---- online softmax (4 threads per row) ----
        {
            float* mrow = (float*)(smc + AM_B);
            float* lrow = (float*)(smc + AL_B);
            float* srow = (float*)(smc + AS_B);
            int row = tid >> 2;
            int q4  = tid & 3;
            float v[16];
            *(float4*)(v)      = *(const float4*)(sS + row * 68 + q4 * 16);
            *(float4*)(v + 4)  = *(const float4*)(sS + row * 68 + q4 * 16 + 4);
            *(float4*)(v + 8)  = *(const float4*)(sS + row * 68 + q4 * 16 + 8);
            *(float4*)(v + 12) = *(const float4*)(sS + row * 68 + q4 * 16 + 12);
#pragma unroll
            for (int i = 0; i < 16; i++) v[i] *= scale;
            if (j == qt) {
#pragma unroll
                for (int i = 0; i < 16; i++)
                    if (q4 * 16 + i > row) v[i] = -1e30f;
            }
            float mo = mrow[row];
            float mx = v[0];
#pragma unroll
            for (int i = 1; i < 16; i++) mx = fmaxf(mx, v[i]);
            mx = fmaxf(mx, __shfl_xor_sync(0xffffffffu, mx, 1));
            mx = fmaxf(mx, __shfl_xor_sync(0xffffffffu, mx, 2));
            float mnew = fmaxf(mo, mx);
            float sum = 0.f;
            unsigned pw[8];
#pragma unroll
            for (int i = 0; i < 8; i++) {
                float p0 = __expf(v[2 * i]     - mnew);
                float p1 = __expf(v[2 * i + 1] - mnew);
                sum += p0 + p1;
                __half2 hp = __floats2half2_rn(p0, p1);
                pw[i] = *(unsigned*)&hp;
            }
            sum += __shfl_xor_sync(0xffffffffu, sum, 1);
            sum += __shfl_xor_sync(0xffffffffu, sum, 2);
            unsigned* sPw = (unsigned*)(smc + ASP_B);
            *(uint4*)(sPw + row * PSW + q4 * 8)     = *(uint4*)(pw);
            *(uint4*)(sPw + row * PSW + q4 * 8 + 4) = *(uint4*)(pw + 4);
            if (q4 == 0) {
                float esc = __expf(mo - mnew);
                mrow[row] = mnew;
                lrow[row] = lrow[row] * esc + sum;
                srow[row] = esc;
            }
        }
        __syncthreads();

        // ---- rescale O, then O += P V ----
        {
            const float* srow = (const float*)(smc + AS_B);
#pragma unroll
            for (int mt = 0; mt < 2; mt++) {
                float e0 = srow[wmp + mt * 16 + lg];
                float e1 = srow[wmp + mt * 16 + lg + 8];
#pragma unroll
                for (int nt = 0; nt < 4; nt++) {
                    oacc[mt][nt][0] *= e0;
                    oacc[mt][nt][1] *= e0;
                    oacc[mt][nt][2] *= e1;
                    oacc[mt][nt][3] *= e1;
                }
            }
        }
        {
            const unsigned* sPw = (const unsigned*)(smc + ASP_B);
            const unsigned vbase = smem_base + AV_B + buf * 17408;
            const int seg = lane >> 3, r = lane & 7;
#pragma unroll
            for (int ks = 0; ks < 4; ks++) {
                unsigned af[2][4];
#pragma unroll
                for (int mt = 0; mt < 2; mt++) {
                    int base = (wmp + mt * 16 + lg) * PSW + ks * 8 + lc;
                    af[mt][0] = sPw[base];
                    af[mt][1] = sPw[base + 8 * PSW];
                    af[mt][2] = sPw[base + 4];
                    af[mt][3] = sPw[base + 8 * PSW + 4];
                }
                unsigned bv[4][2];
#pragma unroll
                for (int p = 0; p < 2; p++) {
                    int row = ks * 16 + (seg & 1) * 8 + r;
                    int col = wnp + p * 16 + (seg >> 1) * 8;
                    ldsm_x4_t(bv[2 * p][0], bv[2 * p][1],
                              bv[2 * p + 1][0], bv[2 * p + 1][1],
                              vbase + (row * KVSTR + col) * 2);
                }
#pragma unroll
                for (int mt = 0; mt < 2; mt++)
#pragma unroll
                    for (int nt = 0; nt < 4; nt++)
                        mma_f16(oacc[mt][nt], af[mt], bv[nt]);
            }
        }
        cp_wait0();
        __syncthreads();
        buf ^= 1;
    }

    // ---- epilogue: divide by l, write g_Oh (half) ----
    {
        const float* lrow = (const float*)(smc + AL_B);
#pragma unroll
        for (int mt = 0; mt < 2; mt++) {
            int r  = wmp + mt * 16 + lg;
            float il0 = 1.0f / lrow[r];
            float il1 = 1.0f / lrow[r + 8];
            int gr = qt * 64 + r;
#pragma unroll
            for (int nt = 0; nt < 4; nt++) {
                int col = h * HDM + wnp + nt * 8 + 2 * lc;
                *(__half2*)(g_Oh + gr * DIMV + col) =
                    __floats2half2_rn(oacc[mt][nt][0] * il0, oacc[mt][nt][1] * il0);
                *(__half2*)(g_Oh + (gr + 8) * DIMV + col) =
                    __floats2half2_rn(oacc[mt][nt][2] * il1, oacc[mt][nt][3] * il1);
            }
        }
    }
}

// ============================================================
// launch
// ============================================================
extern "C" void kernel_launch(void* const* d_in, const int* in_sizes, int n_in,
                              void* d_out, int out_size)
{
    const float* query = (const float*)d_in[0];
    const float* key   = (const float*)d_in[1];
    const float* value = (const float*)d_in[2];
    const float* Wq    = (const float*)d_in[3];
    const float* bq    = (const float*)d_in[4];
    const float* Wk    = (const float*)d_in[5];
    const float* bk    = (const float*)d_in[6];
    const float* Wv    = (const float*)d_in[7];
    const float* bv    = (const float*)d_in[8];
    const float* Wo    = (const float*)d_in[9];
    const float* bo    = (const float*)d_in[10];
    float* out = (float*)d_out;

    cudaFuncSetAttribute((const void*)proj_kernel,
                         cudaFuncAttributeMaxDynamicSharedMemorySize, G_SMEM);
    cudaFuncSetAttribute((const void*)gemm_o_kernel,
                         cudaFuncAttributeMaxDynamicSharedMemorySize, G_SMEM);
    cudaFuncSetAttribute((const void*)attn_kernel,
                         cudaFuncAttributeMaxDynamicSharedMemorySize, ATT_SMEM);

    __half* hq;  cudaGetSymbolAddress((void**)&hq,  h_query);
    __half* hk;  cudaGetSymbolAddress((void**)&hk,  h_key);
    __half* hv;  cudaGetSymbolAddress((void**)&hv,  h_value);
    __half* hwq; cudaGetSymbolAddress((void**)&hwq, h_Wq);
    __half* hwk; cudaGetSymbolAddress((void**)&hwk, h_Wk);
    __half* hwv; cudaGetSymbolAddress((void**)&hwv, h_Wv);
    __half* hwo; cudaGetSymbolAddress((void**)&hwo, h_Wo);

    const int n4_big = (S_LEN * DIMV) / 4;   // 1M
    const int n4_sm  = (KVD * DIMV) / 4;     // 256K
    cvt_half_kernel<<<(n4_big + 255) / 256, 256>>>((const float4*)query, (__half2*)hq,  n4_big);
    cvt_half_kernel<<<(n4_big + 255) / 256, 256>>>((const float4*)key,   (__half2*)hk,  n4_big);
    cvt_half_kernel<<<(n4_big + 255) / 256, 256>>>((const float4*)value, (__half2*)hv,  n4_big);
    cvt_half_kernel<<<(n4_big + 255) / 256, 256>>>((const float4*)Wq,    (__half2*)hwq, n4_big);
    cvt_half_kernel<<<(n4_sm  + 255) / 256, 256>>>((const float4*)Wk,    (__half2*)hwk, n4_sm);
    cvt_half_kernel<<<(n4_sm  + 255) / 256, 256>>>((const float4*)Wv,    (__half2*)hwv, n4_sm);
    cvt_half_kernel<<<(n4_big + 255) / 256, 256>>>((const float4*)Wo,    (__half2*)hwo, n4_big);

    proj_kernel<<<192, 256, G_SMEM>>>(bq, bk, bv);

    {
        const int total = S_LEN * (NQH + NKVH) * 64;
        rope_kernel<<<(total + 255) / 256, 256>>>();
    }

    attn_kernel<<<dim3(32, 16), 256, ATT_SMEM>>>();

    gemm_o_kernel<<<128, 256, G_SMEM>>>(bo, out);
}

// round 8
// speedup vs baseline: 5.6303x; 1.0561x over previous
#include <cuda_runtime.h>
#include <cuda_fp16.h>
#include <math.h>

#define S_LEN   2048
#define DIMV    2048
#define KVD     512
#define NQH     16
#define NKVH    4
#define HDM     128
#define SCALE   0.08838834764831845f   // 1/sqrt(128)

// ---- scratch (no cudaMalloc allowed) ----
__device__ __half h_query[S_LEN * DIMV];
__device__ __half h_key[S_LEN * DIMV];
__device__ __half h_value[S_LEN * DIMV];
__device__ __half h_Wq[DIMV * DIMV];     // pre-scaled by SCALE
__device__ __half h_Wk[KVD * DIMV];
__device__ __half h_Wv[KVD * DIMV];
__device__ __half h_Wo[DIMV * DIMV];
__device__ __half g_Qh[S_LEN * DIMV];
__device__ __half g_Kh[S_LEN * KVD];
__device__ __half g_Vh[S_LEN * KVD];
__device__ __half g_Oh[S_LEN * DIMV];
__device__ float2 g_rope[S_LEN * 64];    // (cos, sin) table

// ============================================================
// helpers
// ============================================================
__device__ __forceinline__ void mma_f16(float* c, const unsigned* a, const unsigned* b) {
    asm volatile(
        "mma.sync.aligned.m16n8k16.row.col.f32.f16.f16.f32 "
        "{%0,%1,%2,%3}, {%4,%5,%6,%7}, {%8,%9}, {%0,%1,%2,%3};"
        : "+f"(c[0]), "+f"(c[1]), "+f"(c[2]), "+f"(c[3])
        : "r"(a[0]), "r"(a[1]), "r"(a[2]), "r"(a[3]), "r"(b[0]), "r"(b[1]));
}

__device__ __forceinline__ void ldsm_x4(
    unsigned& r0, unsigned& r1, unsigned& r2, unsigned& r3, unsigned addr)
{
    asm volatile("ldmatrix.sync.aligned.m8n8.x4.shared.b16 {%0,%1,%2,%3}, [%4];"
        : "=r"(r0), "=r"(r1), "=r"(r2), "=r"(r3) : "r"(addr));
}

__device__ __forceinline__ void ldsm_x4_t(
    unsigned& r0, unsigned& r1, unsigned& r2, unsigned& r3, unsigned addr)
{
    asm volatile("ldmatrix.sync.aligned.m8n8.x4.trans.shared.b16 {%0,%1,%2,%3}, [%4];"
        : "=r"(r0), "=r"(r1), "=r"(r2), "=r"(r3) : "r"(addr));
}

__device__ __forceinline__ void cp16(unsigned dst, const void* src) {
    asm volatile("cp.async.cg.shared.global [%0], [%1], 16;" :: "r"(dst), "l"(src));
}
__device__ __forceinline__ void cp_commit() {
    asm volatile("cp.async.commit_group;");
}
__device__ __forceinline__ void cp_wait0() {
    asm volatile("cp.async.wait_group 0;" ::: "memory");
}

// ============================================================
// fused fp32 -> fp16 convert of all inputs (Wq scaled by SCALE)
// ============================================================
#define N4_BIG ((S_LEN * DIMV) / 4)      // 1048576
#define N4_SM  ((KVD * DIMV) / 4)        // 262144
#define N4_TOT (5 * N4_BIG + 2 * N4_SM)

__global__ void __launch_bounds__(256) cvt_all_kernel(
    const float4* __restrict__ q, const float4* __restrict__ k,
    const float4* __restrict__ v, const float4* __restrict__ wq,
    const float4* __restrict__ wo, const float4* __restrict__ wk,
    const float4* __restrict__ wv)
{
    int i = blockIdx.x * blockDim.x + threadIdx.x;
    if (i >= N4_TOT) return;
    const float4* src;
    __half2* dst;
    float s = 1.0f;
    int off;
    if (i < N4_BIG)           { src = q;  dst = (__half2*)h_query; off = i; }
    else if (i < 2 * N4_BIG)  { src = k;  dst = (__half2*)h_key;   off = i - N4_BIG; }
    else if (i < 3 * N4_BIG)  { src = v;  dst = (__half2*)h_value; off = i - 2 * N4_BIG; }
    else if (i < 4 * N4_BIG)  { src = wq; dst = (__half2*)h_Wq;    off = i - 3 * N4_BIG; s = SCALE; }
    else if (i < 5 * N4_BIG)  { src = wo; dst = (__half2*)h_Wo;    off = i - 4 * N4_BIG; }
    else if (i < 5 * N4_BIG + N4_SM) { src = wk; dst = (__half2*)h_Wk; off = i - 5 * N4_BIG; }
    else                      { src = wv; dst = (__half2*)h_Wv;    off = i - 5 * N4_BIG - N4_SM; }
    float4 val = src[off];
    dst[2 * off]     = __floats2half2_rn(val.x * s, val.y * s);
    dst[2 * off + 1] = __floats2half2_rn(val.z * s, val.w * s);
}

// ============================================================
// fp16 GEMM: C[m][n] = sum_k A[m][k]*B[n][k] + bscale*bias[n]
// BM=128, BN=256, BK=64 halves, 3-stage cp.async, 256thr/8 warps,
// warp tile 64x64, mma.m16n8k16, ldmatrix fragment loads.
// Smem rows stride 72 halves (144B == 16 mod 128 -> ldmatrix
// phases conflict-free). K fixed 2048.
// ============================================================
#define GKH    2048
#define HSTR   72
#define GA_B   18432               // A region bytes (128*72*2)
#define GSTG_B 55296               // stage bytes
#define G_SMEM (3 * GSTG_B)        // 165888

__device__ __forceinline__ void g_issue_h(
    const __half* ag, const __half* bg, unsigned as_, unsigned bs_)
{
#pragma unroll
    for (int i = 0; i < 4; i++)
        cp16(as_ + i * 32 * HSTR * 2, ag + i * 32 * GKH);
#pragma unroll
    for (int i = 0; i < 8; i++)
        cp16(bs_ + i * 32 * HSTR * 2, bg + i * 32 * GKH);
    cp_commit();
}

template <bool HALF_OUT>
__device__ __forceinline__ void gemm_f16_body(
    const __half* __restrict__ A, const __half* __restrict__ B,
    const float* __restrict__ bias, float bscale, void* __restrict__ Cv,
    int N, int bm, int bn)
{
    extern __shared__ char smc[];
    unsigned smem_base = (unsigned)__cvta_generic_to_shared(smc);
    const int tid  = threadIdx.x;
    const int lane = tid & 31;
    const int wid  = tid >> 5;
    const int lg   = lane >> 2;
    const int lc   = lane & 3;
    const int wm   = (wid >> 2) * 64;
    const int wn   = (wid & 3) * 64;

    // ldmatrix per-lane source rows
    const int a_mrow = lane & 15, a_kseg = lane >> 4;                 // A pattern
    const int b_nrow = ((lane >> 4) << 3) + (lane & 7);               // B pattern
    const int b_kseg = (lane >> 3) & 1;

    const int rowb = tid >> 3;
    const int seg  = tid & 7;

    const __half* Ag = A + (bm + rowb) * GKH + seg * 8;
    const __half* Bg = B + (bn + rowb) * GKH + seg * 8;
    const unsigned aoff = (rowb * HSTR + seg * 8) * 2;
    const unsigned boff = GA_B + (rowb * HSTR + seg * 8) * 2;

    float acc[4][8][4];
#pragma unroll
    for (int mt = 0; mt < 4; mt++)
#pragma unroll
        for (int nt = 0; nt < 8; nt++)
#pragma unroll
            for (int c = 0; c < 4; c++) acc[mt][nt][c] = 0.f;

    g_issue_h(Ag,      Bg,      smem_base + aoff,          smem_base + boff);
    g_issue_h(Ag + 64, Bg + 64, smem_base + GSTG_B + aoff, smem_base + GSTG_B + boff);

    const int nIter = GKH / 64;   // 32
    for (int kt = 0; kt < nIter; kt++) {
        asm volatile("cp.async.wait_group 1;" ::: "memory");
        __syncthreads();
        if (kt + 2 < nIter) {
            int s = (kt + 2) % 3;
            g_issue_h(Ag + (kt + 2) * 64, Bg + (kt + 2) * 64,
                      smem_base + s * GSTG_B + aoff,
                      smem_base + s * GSTG_B + boff);
        } else {
            cp_commit();
        }

        const unsigned As_b = smem_base + (kt % 3) * GSTG_B;
        const unsigned Bs_b = As_b + GA_B;
#pragma unroll
        for (int ks = 0; ks < 4; ks++) {
            unsigned af[4][4], bf[8][2];
#pragma unroll
            for (int mt = 0; mt < 4; mt++)
                ldsm_x4(af[mt][0], af[mt][1], af[mt][2], af[mt][3],
                        As_b + ((wm + mt * 16 + a_mrow) * HSTR + ks * 16 + a_kseg * 8) * 2);
#pragma unroll
            for (int np = 0; np < 4; np++)
                ldsm_x4(bf[2 * np][0], bf[2 * np][1], bf[2 * np + 1][0], bf[2 * np + 1][1],
                        Bs_b + ((wn + np * 16 + b_nrow) * HSTR + ks * 16 + b_kseg * 8) * 2);
#pragma unroll
            for (int mt = 0; mt < 4; mt++)
#pragma unroll
                for (int nt = 0; nt < 8; nt++)
                    mma_f16(acc[mt][nt], af[mt], bf[nt]);
        }
    }

#pragma unroll
    for (int mt = 0; mt < 4; mt++) {
        int row = bm + wm + mt * 16 + lg;
#pragma unroll
        for (int nt = 0; nt < 8; nt++) {
            int col = bn + wn + nt * 8 + 2 * lc;
            float b0 = __ldg(bias + col)     * bscale;
            float b1 = __ldg(bias + col + 1) * bscale;
            float o0 = acc[mt][nt][0] + b0, o1 = acc[mt][nt][1] + b1;
            float o2 = acc[mt][nt][2] + b0, o3 = acc[mt][nt][3] + b1;
            if (HALF_OUT) {
                __half* C = (__half*)Cv;
                *(__half2*)(C + row * N + col)       = __floats2half2_rn(o0, o1);
                *(__half2*)(C + (row + 8) * N + col) = __floats2half2_rn(o2, o3);
            } else {
                float* C = (float*)Cv;
                *(float2*)(C + row * N + col)       = make_float2(o0, o1);
                *(float2*)(C + (row + 8) * N + col) = make_float2(o2, o3);
            }
        }
    }
}

// fused Q/K/V projection: blocks 0..127 Q (scaled), 128..159 K, 160..191 V
__global__ void __launch_bounds__(256) proj_kernel(
    const float* __restrict__ bq, const float* __restrict__ bk,
    const float* __restrict__ bv)
{
    int b = blockIdx.x;
    const __half *A, *B;
    const float* bi;
    float bscale = 1.0f;
    __half* C;
    int N, bm, bn;
    if (b < 128) {
        A = h_query; B = h_Wq; bi = bq; C = g_Qh; N = DIMV;
        bm = (b >> 3) * 128; bn = (b & 7) * 256; bscale = SCALE;
    } else if (b < 160) {
        int i = b - 128;
        A = h_key; B = h_Wk; bi = bk; C = g_Kh; N = KVD;
        bm = (i >> 1) * 128; bn = (i & 1) * 256;
    } else {
        int i = b - 160;
        A = h_value; B = h_Wv; bi = bv; C = g_Vh; N = KVD;
        bm = (i >> 1) * 128; bn = (i & 1) * 256;
    }
    gemm_f16_body<true>(A, B, bi, bscale, C, N, bm, bn);
}

__global__ void __launch_bounds__(256) gemm_o_kernel(
    const float* __restrict__ bo, float* __restrict__ out)
{
    int b = blockIdx.x;
    gemm_f16_body<false>(g_Oh, h_Wo, bo, 1.0f, out, DIMV,
                         (b >> 3) * 128, (b & 7) * 256);
}

// ============================================================
// RoPE: table precompute + apply (table is accurate sincosf)
// ============================================================
__global__ void __launch_bounds__(256) rope_tab_kernel()
{
    int idx = blockIdx.x * blockDim.x + threadIdx.x;   // s*64 + j
    if (idx >= S_LEN * 64) return;
    int j = idx & 63;
    int s = idx >> 6;
    float inv = powf(10000.0f, -(float)(2 * j) * (1.0f / 128.0f));
    float sn, cs;
    sincosf((float)s * inv, &sn, &cs);
    g_rope[idx] = make_float2(cs, sn);
}

__global__ void __launch_bounds__(256) rope_kernel()
{
    const int total = S_LEN * (NQH + NKVH) * 64;
    int idx = blockIdx.x * blockDim.x + threadIdx.x;
    if (idx >= total) return;
    int j  = idx & 63;
    int t  = idx >> 6;
    int hh = t % (NQH + NKVH);
    int s  = t / (NQH + NKVH);

    float2 cssn = g_rope[s * 64 + j];

    __half* base = (hh < NQH) ? (g_Qh + s * DIMV + hh * HDM)
                              : (g_Kh + s * KVD + (hh - NQH) * HDM);
    float x1 = __half2float(base[j]);
    float x2 = __half2float(base[j + 64]);
    base[j]      = __float2half_rn(x1 * cssn.x - x2 * cssn.y);
    base[j + 64] = __float2half_rn(x2 * cssn.x + x1 * cssn.y);
}

// ============================================================
// Flash attention, fp16 MMA + ldmatrix, causal GQA.
// BM=BN=64, HD=128, 256 thr / 8 warps. Scale pre-folded into Q.
// ============================================================
#define AQ_B   0
#define AK_B   17408
#define AV_B   52224
#define ASP_B  87040
#define AM_B   96256
#define AL_B   96512
#define AS_B   96768
#define ATT_SMEM 97024
#define KVSTR  136      // halves per K/V/Q smem row (272B == 16 mod 128)
#define PSH    72       // halves per sP row (144B == 16 mod 128)

__device__ __forceinline__ void attn_issue_kv(
    const __half* Kb, const __half* Vb, int j, int buf,
    unsigned smem_base, int tid)
{
    const __half* Ksrc = Kb + (j * 64) * KVD;
    const __half* Vsrc = Vb + (j * 64) * KVD;
    unsigned kb = smem_base + AK_B + buf * 17408;
    unsigned vb = smem_base + AV_B + buf * 17408;
#pragma unroll
    for (int i = 0; i < 4; i++) {
        int c   = tid + i * 256;
        int row = c >> 4;
        int sg  = c & 15;
        cp16(kb + (row * KVSTR + sg * 8) * 2, Ksrc + row * KVD + sg * 8);
        cp16(vb + (row * KVSTR + sg * 8) * 2, Vsrc + row * KVD + sg * 8);
    }
    cp_commit();
}

__global__ void __launch_bounds__(256) attn_kernel()
{
    extern __shared__ char smc[];
    unsigned smem_base = (unsigned)__cvta_generic_to_shared(smc);
    float* sm = (float*)smc;

    const int tid  = threadIdx.x;
    const int lane = tid & 31;
    const int wid  = tid >> 5;
    const int qt   = gridDim.x - 1 - blockIdx.x;
    const int h    = blockIdx.y;
    const int kvh  = h >> 2;
    const int lg   = lane >> 2;
    const int lc   = lane & 3;

    const int a_mrow = lane & 15, a_kseg = lane >> 4;
    const int b_nrow = ((lane >> 4) << 3) + (lane & 7);
    const int b_kseg = (lane >> 3) & 1;

    const int wms = (wid >> 2) * 32;   // S warp tile 32x16
    const int wns = (wid & 3) * 16;
    const int wmp = (wid >> 2) * 32;   // PV warp tile 32x32
    const int wnp = (wid & 3) * 32;

    const __half* Qb = g_Qh + h * HDM;
    const __half* Kb = g_Kh + kvh * HDM;
    const __half* Vb = g_Vh + kvh * HDM;

    attn_issue_kv(Kb, Vb, 0, 0, smem_base, tid);

    {
        const __half* Qsrc = Qb + (qt * 64) * DIMV;
#pragma unroll
        for (int i = 0; i < 4; i++) {
            int c   = tid + i * 256;
            int row = c >> 4;
            int sg  = c & 15;
            cp16(smem_base + AQ_B + (row * KVSTR + sg * 8) * 2,
                 Qsrc + row * DIMV + sg * 8);
        }
        cp_commit();
    }
    {
        float* mrow = (float*)(smc + AM_B);
        float* lrow = (float*)(smc + AL_B);
        if (tid < 64) { mrow[tid] = -1e30f; lrow[tid] = 0.f; }
    }
    cp_wait0();
    __syncthreads();

    // Q fragments -> registers via ldmatrix
    unsigned qf[2][8][4];
#pragma unroll
    for (int mt = 0; mt < 2; mt++)
#pragma unroll
        for (int ks = 0; ks < 8; ks++)
            ldsm_x4(qf[mt][ks][0], qf[mt][ks][1], qf[mt][ks][2], qf[mt][ks][3],
                    smem_base + AQ_B +
                    ((wms + mt * 16 + a_mrow) * KVSTR + ks * 16 + a_kseg * 8) * 2);
    __syncthreads();   // Q region reused as sS

    float oacc[2][4][4];
#pragma unroll
    for (int mt = 0; mt < 2; mt++)
#pragma unroll
        for (int nt = 0; nt < 4; nt++)
#pragma unroll
            for (int c = 0; c < 4; c++) oacc[mt][nt][c] = 0.f;

    int buf = 0;
    for (int j = 0; j <= qt; j++) {
        if (j < qt) attn_issue_kv(Kb, Vb, j + 1, buf ^ 1, smem_base, tid);

        // ---- S = Q K^T ----
        const unsigned kbase = smem_base + AK_B + buf * 17408;
        float sacc[2][2][4];
#pragma unroll
        for (int mt = 0; mt < 2; mt++)
#pragma unroll
            for (int nt = 0; nt < 2; nt++)
#pragma unroll
                for (int c = 0; c < 4; c++) sacc[mt][nt][c] = 0.f;

#pragma unroll
        for (int ks = 0; ks < 8; ks++) {
            unsigned bf[2][2];
            ldsm_x4(bf[0][0], bf[0][1], bf[1][0], bf[1][1],
                    kbase + ((wns + b_nrow) * KVSTR + ks * 16 + b_kseg * 8) * 2);
#pragma unroll
            for (int mt = 0; mt < 2; mt++)
#pragma unroll
                for (int nt = 0; nt < 2; nt++)
                    mma_f16(sacc[mt][nt], qf[mt][ks], bf[nt]);
        }

        float* sS = sm;
#pragma unroll
        for (int mt = 0; mt < 2; mt++) {
            int r0 = wms + mt * 16 + lg;
#pragma unroll
            for (int nt = 0; nt < 2; nt++) {
                int c0 = wns + nt * 8 + 2 * lc;
                *(float2*)(sS + r0 * 68 + c0) =
                    make_float2(sacc[mt][nt][0], sacc[mt][nt][1]);
                *(float2*)(sS + (r0 + 8) * 68 + c0) =
                    make_float2(sacc[mt][nt][2], sacc[mt][nt][3]);
            }
        }
        __syncthreads();

        // ---- online softmax (4 threads per row); scale pre-folded ----
        {
            float* mrow = (float*)(smc + AM_B);
            float* lrow = (float*)(smc + AL_B);
            float* srow = (float*)(smc + AS_B);
            int row = tid >> 2;
            int q4  = tid & 3;
            float v[16];
            *(float4*)(v)      = *(const float4*)(sS + row * 68 + q4 * 16);
            *(float4*)(v + 4)  = *(const float4*)(sS + row * 68 + q4 * 16 + 4);
            *(float4*)(v + 8)  = *(const float4*)(sS + row * 68 + q4 * 16 + 8);
            *(float4*)(v + 12) = *(const float4*)(sS + row * 68 + q4 * 16 + 12);
            if (j == qt) {
#pragma unroll
                for (int i = 0; i < 16; i++)
                    if (q4 * 16 + i > row) v[i] = -1e30f;
            }
            float mo = mrow[row];
            float mx = v[0];
#pragma unroll
            for (int i = 1; i < 16; i++) mx = fmaxf(mx, v[i]);
            mx = fmaxf(mx, __shfl_xor_sync(0xffffffffu, mx, 1));
            mx = fmaxf(mx, __shfl_xor_sync(0xffffffffu, mx, 2));
            float mnew = fmaxf(mo, mx);
            float sum = 0.f;
            unsigned pw[8];
#pragma unroll
            for (int i = 0; i < 8; i++) {
                float p0 = __expf(v[2 * i]     - mnew);
                float p1 = __expf(v[2 * i + 1] - mnew);
                sum += p0 + p1;
                __half2 hp = __floats2half2_rn(p0, p1);
                pw[i] = *(unsigned*)&hp;
            }
            sum += __shfl_xor_sync(0xffffffffu, sum, 1);
            sum += __shfl_xor_sync(0xffffffffu, sum, 2);
            unsigned* sPw = (unsigned*)(smc + ASP_B);
            *(uint4*)(sPw + row * (PSH / 2) + q4 * 8)     = *(uint4*)(pw);
            *(uint4*)(sPw + row * (PSH / 2) + q4 * 8 + 4) = *(uint4*)(pw + 4);
            if (q4 == 0) {
                float esc = __expf(mo - mnew);
                mrow[row] = mnew;
                lrow[row] = lrow[row] * esc + sum;
                srow[row] = esc;
            }
        }
        __syncthreads();

        // ---- rescale O, then O += P V ----
        {
            const float* srow = (const float*)(smc + AS_B);
#pragma unroll
            for (int mt = 0; mt < 2; mt++) {
                float e0 = srow[wmp + mt * 16 + lg];
                float e1 = srow[wmp + mt * 16 + lg + 8];
#pragma unroll
                for (int nt = 0; nt < 4; nt++) {
                    oacc[mt][nt][0] *= e0;
                    oacc[mt][nt][1] *= e0;
                    oacc[mt][nt][2] *= e1;
                    oacc[mt][nt][3] *= e1;
                }
            }
        }
        {
            const unsigned pbase = smem_base + ASP_B;
            const unsigned vbase = smem_base + AV_B + buf * 17408;
            const int seg = lane >> 3, r = lane & 7;
#pragma unroll
            for (int ks = 0; ks < 4; ks++) {
                unsigned af[2][4];
#pragma unroll
                for (int mt = 0; mt < 2; mt++)
                    ldsm_x4(af[mt][0], af[mt][1], af[mt][2], af[mt][3],
                            pbase + ((wmp + mt * 16 + a_mrow) * PSH + ks * 16 + a_kseg * 8) * 2);
                unsigned bv[4][2];
#pragma unroll
                for (int p = 0; p < 2; p++) {
                    int row = ks * 16 + (seg & 1) * 8 + r;
                    int col = wnp + p * 16 + (seg >> 1) * 8;
                    ldsm_x4_t(bv[2 * p][0], bv[2 * p][1],
                              bv[2 * p + 1][0], bv[2 * p + 1][1],
                              vbase + (row * KVSTR + col) * 2);
                }
#pragma unroll
                for (int mt = 0; mt < 2; mt++)
#pragma unroll
                    for (int nt = 0; nt < 4; nt++)
                        mma_f16(oacc[mt][nt], af[mt], bv[nt]);
            }
        }
        cp_wait0();
        __syncthreads();
        buf ^= 1;
    }

    // ---- epilogue ----
    {
        const float* lrow = (const float*)(smc + AL_B);
#pragma unroll
        for (int mt = 0; mt < 2; mt++) {
            int r  = wmp + mt * 16 + lg;
            float il0 = 1.0f / lrow[r];
            float il1 = 1.0f / lrow[r + 8];
            int gr = qt * 64 + r;
#pragma unroll
            for (int nt = 0; nt < 4; nt++) {
                int col = h * HDM + wnp + nt * 8 + 2 * lc;
                *(__half2*)(g_Oh + gr * DIMV + col) =
                    __floats2half2_rn(oacc[mt][nt][0] * il0, oacc[mt][nt][1] * il0);
                *(__half2*)(g_Oh + (gr + 8) * DIMV + col) =
                    __floats2half2_rn(oacc[mt][nt][2] * il1, oacc[mt][nt][3] * il1);
            }
        }
    }
}

// ============================================================
// launch
// ============================================================
extern "C" void kernel_launch(void* const* d_in, const int* in_sizes, int n_in,
                              void* d_out, int out_size)
{
    const float* query = (const float*)d_in[0];
    const float* key   = (const float*)d_in[1];
    const float* value = (const float*)d_in[2];
    const float* Wq    = (const float*)d_in[3];
    const float* bq    = (const float*)d_in[4];
    const float* Wk    = (const float*)d_in[5];
    const float* bk    = (const float*)d_in[6];
    const float* Wv    = (const float*)d_in[7];
    const float* bv    = (const float*)d_in[8];
    const float* Wo    = (const float*)d_in[9];
    const float* bo    = (const float*)d_in[10];
    float* out = (float*)d_out;

    cudaFuncSetAttribute((const void*)proj_kernel,
                         cudaFuncAttributeMaxDynamicSharedMemorySize, G_SMEM);
    cudaFuncSetAttribute((const void*)gemm_o_kernel,
                         cudaFuncAttributeMaxDynamicSharedMemorySize, G_SMEM);
    cudaFuncSetAttribute((const void*)attn_kernel,
                         cudaFuncAttributeMaxDynamicSharedMemorySize, ATT_SMEM);

    cvt_all_kernel<<<(N4_TOT + 255) / 256, 256>>>(
        (const float4*)query, (const float4*)key, (const float4*)value,
        (const float4*)Wq, (const float4*)Wo, (const float4*)Wk, (const float4*)Wv);

    rope_tab_kernel<<<(S_LEN * 64 + 255) / 256, 256>>>();

    proj_kernel<<<192, 256, G_SMEM>>>(bq, bk, bv);

    {
        const int total = S_LEN * (NQH + NKVH) * 64;
        rope_kernel<<<(total + 255) / 256, 256>>>();
    }

    attn_kernel<<<dim3(32, 16), 256, ATT_SMEM>>>();

    gemm_o_kernel<<<128, 256, G_SMEM>>>(bo, out);
}